// round 8
// baseline (speedup 1.0000x reference)
#include <cuda_runtime.h>
#include <cuda_fp16.h>
#include <math_constants.h>
#include <cstdint>

#define NUM_HEADS 8
#define TOPK 4
#define D_MODEL 128
#define CH 16
#define P2 64
#define NVIEW 2
#define SCALE_LOG2E ((float)(0.08838834764831845 * 1.4426950408889634))
#define KST 24   // kv_s row stride (halves): word=(8nt+lr)*12+q4 -> 32 distinct banks
#define VST 72   // vt_s row stride (halves): word=(4lr+q4) mod 32 -> conflict-free

// partial window sums (combined in topk; scaling dropped: argmax-invariant)
__device__ float g_qp[2][P2 * D_MODEL];
__device__ float g_kp[2][NVIEW * P2 * D_MODEL];
__device__ int   g_ridx[P2 * TOPK];

__device__ __forceinline__ uint32_t ex2_h2(uint32_t x) {
    uint32_t r;
    asm("ex2.approx.f16x2 %0, %1;" : "=r"(r) : "r"(x));
    return r;
}

// QK: f16 accumulator (single MMA per S-tile -> one rounding, same as cvt path)
__device__ __forceinline__ void mma_s16(uint32_t d[2], const uint32_t a[4],
                                        uint32_t b0, uint32_t b1) {
    uint32_t z = 0;
    asm volatile(
        "mma.sync.aligned.m16n8k16.row.col.f16.f16.f16.f16 "
        "{%0,%1}, {%2,%3,%4,%5}, {%6,%7}, {%8,%9};"
        : "=r"(d[0]), "=r"(d[1])
        : "r"(a[0]), "r"(a[1]), "r"(a[2]), "r"(a[3]),
          "r"(b0), "r"(b1), "r"(z), "r"(z));
}

// PV: f32 accumulator (precision across 1024 kv)
__device__ __forceinline__ void mma_f16(float d[4], const uint32_t a[4],
                                        uint32_t b0, uint32_t b1, const float c[4]) {
    asm volatile(
        "mma.sync.aligned.m16n8k16.row.col.f32.f16.f16.f32 "
        "{%0,%1,%2,%3}, {%4,%5,%6,%7}, {%8,%9}, {%10,%11,%12,%13};"
        : "=f"(d[0]), "=f"(d[1]), "=f"(d[2]), "=f"(d[3])
        : "r"(a[0]), "r"(a[1]), "r"(a[2]), "r"(a[3]), "r"(b0), "r"(b1),
          "f"(c[0]), "f"(c[1]), "f"(c[2]), "f"(c[3]));
}

// ---------------------------------------------------------------------------
// Kernel 1: half-window partial sums. 384 blocks x 512 threads.
// ---------------------------------------------------------------------------
__global__ void win_mean_kernel(const float* __restrict__ cv,
                                const float* __restrict__ mv) {
    __shared__ float4 red[512];
    int b = blockIdx.x;
    int t = threadIdx.x;
    int c4 = t & 31, part = t >> 5;    // 16 parts x 8 pixels
    const float* src;
    float* dst;
    int p, half;
    if (b < 128) {
        p = b >> 1; half = b & 1;
        src = cv;
        dst = g_qp[half] + p * D_MODEL;
    } else {
        int vp = b - 128;
        int idx = vp >> 1; half = vp & 1;
        int v = idx >> 6; p = idx & 63;
        src = mv + (size_t)v * 128 * 128 * 128;
        dst = g_kp[half] + idx * D_MODEL;
    }
    int jp = p >> 3, ip = p & 7;
    float4 s = make_float4(0.f, 0.f, 0.f, 0.f);
    #pragma unroll
    for (int u = 0; u < 8; u++) {
        int pix = half * 128 + part * 8 + u;
        int hh = pix >> 4, ww = pix & 15;
        float4 x = *(reinterpret_cast<const float4*>(
            src + ((size_t)(jp * 16 + hh) * 128 + (ip * 16 + ww)) * 128) + c4);
        s.x += x.x; s.y += x.y; s.z += x.z; s.w += x.w;
    }
    red[t] = s;
    __syncthreads();
    if (t < 32) {
        float4 acc = make_float4(0.f, 0.f, 0.f, 0.f);
        #pragma unroll
        for (int k = 0; k < 16; k++) {
            float4 x = red[k * 32 + t];
            acc.x += x.x; acc.y += x.y; acc.z += x.z; acc.w += x.w;
        }
        reinterpret_cast<float4*>(dst)[t] = acc;
    }
}

// ---------------------------------------------------------------------------
// Kernel 2: routing + top-4 (combines partials; positive scalings dropped)
// ---------------------------------------------------------------------------
__global__ void topk_kernel() {
    __shared__ float q_s[8 * D_MODEL];
    int t = threadIdx.x;
    int warp = t >> 5, lane = t & 31;
    int row = blockIdx.x * 8 + warp;

    for (int i = t; i < 8 * D_MODEL; i += 256) {
        int off = blockIdx.x * 8 * D_MODEL + i;
        q_s[i] = g_qp[0][off] + g_qp[1][off];
    }
    __syncthreads();

    float v[4]; int id[4];
    const float* qr = q_s + warp * D_MODEL;
    #pragma unroll
    for (int kloc = 0; kloc < 4; kloc++) {
        int j = lane * 4 + kloc;
        const float* kr0 = g_kp[0] + j * D_MODEL;
        const float* kr1 = g_kp[1] + j * D_MODEL;
        float s = 0.f;
        #pragma unroll 8
        for (int c = 0; c < D_MODEL; c++) s += qr[c] * (kr0[c] + kr1[c]);
        v[kloc] = s; id[kloc] = j;
    }
    #pragma unroll
    for (int r = 0; r < TOPK; r++) {
        float bv = v[0]; int bi = id[0];
        #pragma unroll
        for (int kloc = 1; kloc < 4; kloc++)
            if (v[kloc] > bv || (v[kloc] == bv && id[kloc] < bi)) { bv = v[kloc]; bi = id[kloc]; }
        float wv = bv; int wi = bi;
        #pragma unroll
        for (int off = 16; off; off >>= 1) {
            float ov = __shfl_down_sync(0xffffffffu, wv, off);
            int   oi = __shfl_down_sync(0xffffffffu, wi, off);
            if (ov > wv || (ov == wv && oi < wi)) { wv = ov; wi = oi; }
        }
        wi = __shfl_sync(0xffffffffu, wi, 0);
        if ((wi >> 2) == lane) v[wi & 3] = -CUDART_INF_F;
        if (lane == 0) g_ridx[row * TOPK + r] = wi;
    }
}

// ---------------------------------------------------------------------------
// Kernel 3: fp16 attention, no-max softmax. QK with f16 accum (S c-frag ==
// PV a-frag after in-place ex2.f16x2). Grid (64,8,2), 256 threads / 8 warps,
// 2 CTAs per SM (128-reg cap: no spills).
// ---------------------------------------------------------------------------
__global__ void __launch_bounds__(256, 2)
attn_kernel(const float* __restrict__ cv,
            const float* __restrict__ mv,
            float* __restrict__ out) {
    int p = blockIdx.x;      // window
    int m = blockIdx.y;      // head
    int half = blockIdx.z;   // which 128 query rows
    int t = threadIdx.x;
    int warp = t >> 5, lane = t & 31;
    int lr = lane >> 2, q4 = lane & 3;

    __shared__ __half q_s[128 * CH];         // 4 KB
    __shared__ __half kv_s[2][64 * KST];     // 2 x 3 KB (k-major, padded)
    __shared__ __half vt_s[2][CH * VST];     // 2 x 2.25 KB (transposed)
    __shared__ int sel_s[TOPK];

    int jp = p >> 3, ip = p & 7;

    // ---- stage Q ----
    if (t < 128) {
        int pix = half * 128 + t;
        int hh = pix >> 4, ww = pix & 15;
        const float4* gp = reinterpret_cast<const float4*>(
            cv + ((size_t)(jp * 16 + hh) * 128 + (ip * 16 + ww)) * 128 + m * CH);
        float4 x0 = gp[0], x1 = gp[1], x2 = gp[2], x3 = gp[3];
        const float s = SCALE_LOG2E;
        __half2* dst = reinterpret_cast<__half2*>(q_s + t * CH);
        dst[0] = __floats2half2_rn(x0.x * s, x0.y * s);
        dst[1] = __floats2half2_rn(x0.z * s, x0.w * s);
        dst[2] = __floats2half2_rn(x1.x * s, x1.y * s);
        dst[3] = __floats2half2_rn(x1.z * s, x1.w * s);
        dst[4] = __floats2half2_rn(x2.x * s, x2.y * s);
        dst[5] = __floats2half2_rn(x2.z * s, x2.w * s);
        dst[6] = __floats2half2_rn(x3.x * s, x3.y * s);
        dst[7] = __floats2half2_rn(x3.z * s, x3.w * s);
    }
    if (t < TOPK) sel_s[t] = g_ridx[p * TOPK + t];
    __syncthreads();

    int sel[TOPK];
    #pragma unroll
    for (int k = 0; k < TOPK; k++) sel[k] = sel_s[k];

    // ---- Q a-frag ----
    uint32_t qa[4];
    {
        int r0 = warp * 16 + lr;
        qa[0] = *reinterpret_cast<const uint32_t*>(q_s + r0 * CH + 2 * q4);
        qa[1] = *reinterpret_cast<const uint32_t*>(q_s + (r0 + 8) * CH + 2 * q4);
        qa[2] = *reinterpret_cast<const uint32_t*>(q_s + r0 * CH + 8 + 2 * q4);
        qa[3] = *reinterpret_cast<const uint32_t*>(q_s + (r0 + 8) * CH + 8 + 2 * q4);
    }

    // staging roles: 256 threads = 32 pixel-slots x 8 ch-pairs; 2 pixels each
    int pixg = t >> 3;
    int cg   = t & 7;

    float o[2][4];
    float ls0 = 0.f, ls1 = 0.f;
    #pragma unroll
    for (int u = 0; u < 4; u++) { o[0][u] = 0.f; o[1][u] = 0.f; }

    auto ldchunk = [&](int c, float2& fa, float2& fb) {
        int s = sel[c >> 2];
        int jv = (s & 63) >> 3, iv = s & 7;
        const float* base = mv + (size_t)(s >> 6) * 128 * 128 * 128;
        int p0 = (c & 3) * 64 + pixg;
        int p1 = p0 + 32;
        int y0v = jv * 16 + (p0 >> 4), x0v = iv * 16 + (p0 & 15);
        int y1v = jv * 16 + (p1 >> 4), x1v = iv * 16 + (p1 & 15);
        fa = *reinterpret_cast<const float2*>(
            base + ((size_t)y0v * 128 + x0v) * 128 + m * CH + cg * 2);
        fb = *reinterpret_cast<const float2*>(
            base + ((size_t)y1v * 128 + x1v) * 128 + m * CH + cg * 2);
    };
    auto stchunk = [&](int buf, float2 fa, float2 fb) {
        __half2 ha = __floats2half2_rn(fa.x, fa.y);
        __half2 hb = __floats2half2_rn(fb.x, fb.y);
        *reinterpret_cast<__half2*>(kv_s[buf] + pixg * KST + cg * 2) = ha;
        *reinterpret_cast<__half2*>(kv_s[buf] + (pixg + 32) * KST + cg * 2) = hb;
        vt_s[buf][(cg * 2) * VST + pixg]          = __low2half(ha);
        vt_s[buf][(cg * 2 + 1) * VST + pixg]      = __high2half(ha);
        vt_s[buf][(cg * 2) * VST + pixg + 32]     = __low2half(hb);
        vt_s[buf][(cg * 2 + 1) * VST + pixg + 32] = __high2half(hb);
    };

    {
        float2 fa, fb;
        ldchunk(0, fa, fb);
        stchunk(0, fa, fb);
    }
    __syncthreads();

    for (int c = 0; c < 16; c++) {
        int cur = c & 1;
        float2 nfa, nfb;
        if (c + 1 < 16) ldchunk(c + 1, nfa, nfb);   // LDG overlaps compute

        // ---- S = Q K^T (f16 accum, base-2 log domain) ----
        uint32_t pv[8][2];   // S c-frags, become P a-frags in place
        #pragma unroll
        for (int nt = 0; nt < 8; nt++) {
            const __half* kr = kv_s[cur] + (nt * 8 + lr) * KST;
            uint32_t b0 = *reinterpret_cast<const uint32_t*>(kr + 2 * q4);
            uint32_t b1 = *reinterpret_cast<const uint32_t*>(kr + 8 + 2 * q4);
            mma_s16(pv[nt], qa, b0, b1);
        }

        // ---- P = 2^S in place ----
        #pragma unroll
        for (int nt = 0; nt < 8; nt++) {
            pv[nt][0] = ex2_h2(pv[nt][0]);
            pv[nt][1] = ex2_h2(pv[nt][1]);
        }

        // ---- row sums: one f16 add level, then f32 ----
        #pragma unroll
        for (int i = 0; i < 4; i++) {
            __half2 a0 = __hadd2(*reinterpret_cast<__half2*>(&pv[2 * i][0]),
                                 *reinterpret_cast<__half2*>(&pv[2 * i + 1][0]));
            __half2 a1 = __hadd2(*reinterpret_cast<__half2*>(&pv[2 * i][1]),
                                 *reinterpret_cast<__half2*>(&pv[2 * i + 1][1]));
            float2 f0 = __half22float2(a0);
            float2 f1 = __half22float2(a1);
            ls0 += f0.x + f0.y;
            ls1 += f1.x + f1.y;
        }

        // ---- O += P V ----
        #pragma unroll
        for (int ks = 0; ks < 4; ks++) {
            const uint32_t* pa = &pv[2 * ks][0];
            #pragma unroll
            for (int nc = 0; nc < 2; nc++) {
                const __half* vr = vt_s[cur] + (nc * 8 + lr) * VST + ks * 16;
                uint32_t b0 = *reinterpret_cast<const uint32_t*>(vr + 2 * q4);
                uint32_t b1 = *reinterpret_cast<const uint32_t*>(vr + 8 + 2 * q4);
                mma_f16(o[nc], pa, b0, b1, o[nc]);
            }
        }

        if (c + 1 < 16) stchunk((c + 1) & 1, nfa, nfb);
        __syncthreads();
    }

    // ---- epilogue ----
    ls0 += __shfl_xor_sync(0xffffffffu, ls0, 1);
    ls0 += __shfl_xor_sync(0xffffffffu, ls0, 2);
    ls1 += __shfl_xor_sync(0xffffffffu, ls1, 1);
    ls1 += __shfl_xor_sync(0xffffffffu, ls1, 2);

    #pragma unroll
    for (int h = 0; h < 2; h++) {
        float inv = 1.f / (h ? ls1 : ls0);
        int pix = half * 128 + warp * 16 + h * 8 + lr;
        int hh = pix >> 4, ww = pix & 15;
        float* op = out + ((size_t)(jp * 16 + hh) * 128 + (ip * 16 + ww)) * 128 + m * CH;
        #pragma unroll
        for (int nc = 0; nc < 2; nc++) {
            float2 st;
            st.x = o[nc][2 * h]     * inv;
            st.y = o[nc][2 * h + 1] * inv;
            *reinterpret_cast<float2*>(op + nc * 8 + 2 * q4) = st;
        }
    }
}

extern "C" void kernel_launch(void* const* d_in, const int* in_sizes, int n_in,
                              void* d_out, int out_size) {
    const float* cv = (const float*)d_in[0];   // (1,128,128,128)
    const float* mv = (const float*)d_in[1];   // (1,2,128,128,128)
    float* out = (float*)d_out;                // (1,128,128,128)

    win_mean_kernel<<<384, 512>>>(cv, mv);
    topk_kernel<<<8, 256>>>();
    dim3 grid(P2, NUM_HEADS, 2);
    attn_kernel<<<grid, 256>>>(cv, mv, out);
}

// round 9
// speedup vs baseline: 1.0024x; 1.0024x over previous
#include <cuda_runtime.h>
#include <cuda_fp16.h>
#include <math_constants.h>
#include <cstdint>

#define NUM_HEADS 8
#define TOPK 4
#define D_MODEL 128
#define CH 16
#define P2 64
#define NVIEW 2
#define SCALE_LOG2E ((float)(0.08838834764831845 * 1.4426950408889634))
#define KST 24   // kv_s row stride (halves): word=(row)*12+q4 -> 32 distinct banks
#define VST 72   // vt_s row stride (halves): word=(4lr+q4) mod 32 -> conflict-free

// partial window sums (combined in topk; scaling dropped: argmax-invariant)
__device__ float g_qp[2][P2 * D_MODEL];
__device__ float g_kp[2][NVIEW * P2 * D_MODEL];
__device__ int   g_ridx[P2 * TOPK];

// pack two f32 -> half2 -> 2^x (one cvt + one MUFU for two elements)
__device__ __forceinline__ uint32_t p_ex2(float lo, float hi) {
    uint32_t r;
    asm("{\n\t.reg .b32 t;\n\t"
        "cvt.rn.f16x2.f32 t, %2, %1;\n\t"
        "ex2.approx.f16x2 %0, t;\n\t}"
        : "=r"(r) : "f"(lo), "f"(hi));
    return r;
}

// f32 accumulator mma (the fast path on sm_103a legacy tensor pipe)
__device__ __forceinline__ void mma_f16(float d[4], const uint32_t a[4],
                                        uint32_t b0, uint32_t b1, const float c[4]) {
    asm volatile(
        "mma.sync.aligned.m16n8k16.row.col.f32.f16.f16.f32 "
        "{%0,%1,%2,%3}, {%4,%5,%6,%7}, {%8,%9}, {%10,%11,%12,%13};"
        : "=f"(d[0]), "=f"(d[1]), "=f"(d[2]), "=f"(d[3])
        : "r"(a[0]), "r"(a[1]), "r"(a[2]), "r"(a[3]), "r"(b0), "r"(b1),
          "f"(c[0]), "f"(c[1]), "f"(c[2]), "f"(c[3]));
}

// ---------------------------------------------------------------------------
// Kernel 1: half-window partial sums. 384 blocks x 512 threads.
// ---------------------------------------------------------------------------
__global__ void win_mean_kernel(const float* __restrict__ cv,
                                const float* __restrict__ mv) {
    __shared__ float4 red[512];
    int b = blockIdx.x;
    int t = threadIdx.x;
    int c4 = t & 31, part = t >> 5;    // 16 parts x 8 pixels
    const float* src;
    float* dst;
    int p, half;
    if (b < 128) {
        p = b >> 1; half = b & 1;
        src = cv;
        dst = g_qp[half] + p * D_MODEL;
    } else {
        int vp = b - 128;
        int idx = vp >> 1; half = vp & 1;
        int v = idx >> 6; p = idx & 63;
        src = mv + (size_t)v * 128 * 128 * 128;
        dst = g_kp[half] + idx * D_MODEL;
    }
    int jp = p >> 3, ip = p & 7;
    float4 s = make_float4(0.f, 0.f, 0.f, 0.f);
    #pragma unroll
    for (int u = 0; u < 8; u++) {
        int pix = half * 128 + part * 8 + u;
        int hh = pix >> 4, ww = pix & 15;
        float4 x = *(reinterpret_cast<const float4*>(
            src + ((size_t)(jp * 16 + hh) * 128 + (ip * 16 + ww)) * 128) + c4);
        s.x += x.x; s.y += x.y; s.z += x.z; s.w += x.w;
    }
    red[t] = s;
    __syncthreads();
    if (t < 32) {
        float4 acc = make_float4(0.f, 0.f, 0.f, 0.f);
        #pragma unroll
        for (int k = 0; k < 16; k++) {
            float4 x = red[k * 32 + t];
            acc.x += x.x; acc.y += x.y; acc.z += x.z; acc.w += x.w;
        }
        reinterpret_cast<float4*>(dst)[t] = acc;
    }
}

// ---------------------------------------------------------------------------
// Kernel 2: routing + top-4 (combines partials; positive scalings dropped)
// ---------------------------------------------------------------------------
__global__ void topk_kernel() {
    __shared__ float q_s[8 * D_MODEL];
    int t = threadIdx.x;
    int warp = t >> 5, lane = t & 31;
    int row = blockIdx.x * 8 + warp;

    for (int i = t; i < 8 * D_MODEL; i += 256) {
        int off = blockIdx.x * 8 * D_MODEL + i;
        q_s[i] = g_qp[0][off] + g_qp[1][off];
    }
    __syncthreads();

    float v[4]; int id[4];
    const float* qr = q_s + warp * D_MODEL;
    #pragma unroll
    for (int kloc = 0; kloc < 4; kloc++) {
        int j = lane * 4 + kloc;
        const float* kr0 = g_kp[0] + j * D_MODEL;
        const float* kr1 = g_kp[1] + j * D_MODEL;
        float s = 0.f;
        #pragma unroll 8
        for (int c = 0; c < D_MODEL; c++) s += qr[c] * (kr0[c] + kr1[c]);
        v[kloc] = s; id[kloc] = j;
    }
    #pragma unroll
    for (int r = 0; r < TOPK; r++) {
        float bv = v[0]; int bi = id[0];
        #pragma unroll
        for (int kloc = 1; kloc < 4; kloc++)
            if (v[kloc] > bv || (v[kloc] == bv && id[kloc] < bi)) { bv = v[kloc]; bi = id[kloc]; }
        float wv = bv; int wi = bi;
        #pragma unroll
        for (int off = 16; off; off >>= 1) {
            float ov = __shfl_down_sync(0xffffffffu, wv, off);
            int   oi = __shfl_down_sync(0xffffffffu, wi, off);
            if (ov > wv || (ov == wv && oi < wi)) { wv = ov; wi = oi; }
        }
        wi = __shfl_sync(0xffffffffu, wi, 0);
        if ((wi >> 2) == lane) v[wi & 3] = -CUDART_INF_F;
        if (lane == 0) g_ridx[row * TOPK + r] = wi;
    }
}

// ---------------------------------------------------------------------------
// Kernel 3: fp16 attention, no-max softmax, f32-accum QK (fast mma path).
// 8 outer chunks of 128 kv rows, TWO 64-row compute passes per barrier.
// Grid (64,8,2), 256 threads / 8 warps x 16 q-rows, 2 CTAs per SM.
// ---------------------------------------------------------------------------
__global__ void __launch_bounds__(256, 2)
attn_kernel(const float* __restrict__ cv,
            const float* __restrict__ mv,
            float* __restrict__ out) {
    int p = blockIdx.x;      // window
    int m = blockIdx.y;      // head
    int half = blockIdx.z;   // which 128 query rows
    int t = threadIdx.x;
    int warp = t >> 5, lane = t & 31;
    int lr = lane >> 2, q4 = lane & 3;

    __shared__ __half q_s[128 * CH];          // 4 KB
    __shared__ __half kv_s[2][128 * KST];     // 2 x 6 KB (k-major, padded)
    __shared__ __half vt_s[2][2][CH * VST];   // 2 buf x 2 sub x 2.25 KB
    __shared__ int sel_s[TOPK];

    int jp = p >> 3, ip = p & 7;

    // ---- stage Q ----
    if (t < 128) {
        int pix = half * 128 + t;
        int hh = pix >> 4, ww = pix & 15;
        const float4* gp = reinterpret_cast<const float4*>(
            cv + ((size_t)(jp * 16 + hh) * 128 + (ip * 16 + ww)) * 128 + m * CH);
        float4 x0 = gp[0], x1 = gp[1], x2 = gp[2], x3 = gp[3];
        const float s = SCALE_LOG2E;
        __half2* dst = reinterpret_cast<__half2*>(q_s + t * CH);
        dst[0] = __floats2half2_rn(x0.x * s, x0.y * s);
        dst[1] = __floats2half2_rn(x0.z * s, x0.w * s);
        dst[2] = __floats2half2_rn(x1.x * s, x1.y * s);
        dst[3] = __floats2half2_rn(x1.z * s, x1.w * s);
        dst[4] = __floats2half2_rn(x2.x * s, x2.y * s);
        dst[5] = __floats2half2_rn(x2.z * s, x2.w * s);
        dst[6] = __floats2half2_rn(x3.x * s, x3.y * s);
        dst[7] = __floats2half2_rn(x3.z * s, x3.w * s);
    }
    if (t < TOPK) sel_s[t] = g_ridx[p * TOPK + t];
    __syncthreads();

    int sel[TOPK];
    #pragma unroll
    for (int k = 0; k < TOPK; k++) sel[k] = sel_s[k];

    // ---- Q a-frag ----
    uint32_t qa[4];
    {
        int r0 = warp * 16 + lr;
        qa[0] = *reinterpret_cast<const uint32_t*>(q_s + r0 * CH + 2 * q4);
        qa[1] = *reinterpret_cast<const uint32_t*>(q_s + (r0 + 8) * CH + 2 * q4);
        qa[2] = *reinterpret_cast<const uint32_t*>(q_s + r0 * CH + 8 + 2 * q4);
        qa[3] = *reinterpret_cast<const uint32_t*>(q_s + (r0 + 8) * CH + 8 + 2 * q4);
    }

    // staging roles: 256 threads = 32 pixel-slots x 8 ch-pairs; 4 pixels each
    int pixg = t >> 3;
    int cg   = t & 7;

    float o[2][4];
    float ls0 = 0.f, ls1 = 0.f;
    #pragma unroll
    for (int u = 0; u < 4; u++) { o[0][u] = 0.f; o[1][u] = 0.f; }

    // outer chunk c covers kv rows [c*128, c*128+128): window sel[c>>1],
    // group offset (c&1)*128
    auto ldchunk = [&](int c, float2 f[4]) {
        int s = sel[c >> 1];
        int jv = (s & 63) >> 3, iv = s & 7;
        const float* base = mv + (size_t)(s >> 6) * 128 * 128 * 128;
        int goff = (c & 1) * 128;
        #pragma unroll
        for (int k = 0; k < 4; k++) {
            int pixl = goff + pixg + 32 * k;
            int yy = jv * 16 + (pixl >> 4), xx = iv * 16 + (pixl & 15);
            f[k] = *reinterpret_cast<const float2*>(
                base + ((size_t)yy * 128 + xx) * 128 + m * CH + cg * 2);
        }
    };
    auto stchunk = [&](int buf, const float2 f[4]) {
        #pragma unroll
        for (int k = 0; k < 4; k++) {
            int pix = pixg + 32 * k;
            __half2 h = __floats2half2_rn(f[k].x, f[k].y);
            *reinterpret_cast<__half2*>(kv_s[buf] + pix * KST + cg * 2) = h;
            __half* vt = vt_s[buf][k >> 1];
            int col = pix & 63;
            vt[(cg * 2) * VST + col]     = __low2half(h);
            vt[(cg * 2 + 1) * VST + col] = __high2half(h);
        }
    };

    {
        float2 f[4];
        ldchunk(0, f);
        stchunk(0, f);
    }
    __syncthreads();

    for (int c = 0; c < 8; c++) {
        int cur = c & 1;
        float2 nf[4];
        if (c + 1 < 8) ldchunk(c + 1, nf);   // LDG overlaps 2 compute passes

        #pragma unroll
        for (int j = 0; j < 2; j++) {
            // ---- S = Q K^T over 64-row sub-chunk (f32 accum) ----
            float sc[8][4];
            #pragma unroll
            for (int nt = 0; nt < 8; nt++)
                #pragma unroll
                for (int u = 0; u < 4; u++) sc[nt][u] = 0.f;
            #pragma unroll
            for (int nt = 0; nt < 8; nt++) {
                const __half* kr = kv_s[cur] + (j * 64 + nt * 8 + lr) * KST;
                uint32_t b0 = *reinterpret_cast<const uint32_t*>(kr + 2 * q4);
                uint32_t b1 = *reinterpret_cast<const uint32_t*>(kr + 8 + 2 * q4);
                mma_f16(sc[nt], qa, b0, b1, sc[nt]);
            }

            // ---- P = 2^S packed into fp16 a-frags ----
            uint32_t pa[4][4];
            #pragma unroll
            for (int ks = 0; ks < 4; ks++) {
                pa[ks][0] = p_ex2(sc[2 * ks][0],     sc[2 * ks][1]);
                pa[ks][1] = p_ex2(sc[2 * ks][2],     sc[2 * ks][3]);
                pa[ks][2] = p_ex2(sc[2 * ks + 1][0], sc[2 * ks + 1][1]);
                pa[ks][3] = p_ex2(sc[2 * ks + 1][2], sc[2 * ks + 1][3]);
            }

            // ---- row sums: one f16 add level, then f32 ----
            #pragma unroll
            for (int i = 0; i < 4; i++) {
                __half2 a0 = __hadd2(*reinterpret_cast<__half2*>(&pa[i][0]),
                                     *reinterpret_cast<__half2*>(&pa[i][2]));
                __half2 a1 = __hadd2(*reinterpret_cast<__half2*>(&pa[i][1]),
                                     *reinterpret_cast<__half2*>(&pa[i][3]));
                float2 f0 = __half22float2(a0);
                float2 f1 = __half22float2(a1);
                ls0 += f0.x + f0.y;
                ls1 += f1.x + f1.y;
            }

            // ---- O += P V ----
            #pragma unroll
            for (int ks = 0; ks < 4; ks++) {
                #pragma unroll
                for (int nc = 0; nc < 2; nc++) {
                    const __half* vr = vt_s[cur][j] + (nc * 8 + lr) * VST + ks * 16;
                    uint32_t b0 = *reinterpret_cast<const uint32_t*>(vr + 2 * q4);
                    uint32_t b1 = *reinterpret_cast<const uint32_t*>(vr + 8 + 2 * q4);
                    mma_f16(o[nc], pa[ks], b0, b1, o[nc]);
                }
            }
        }

        if (c + 1 < 8) stchunk(cur ^ 1, nf);
        __syncthreads();
    }

    // ---- epilogue: quad-reduce row sums, normalize, store ----
    ls0 += __shfl_xor_sync(0xffffffffu, ls0, 1);
    ls0 += __shfl_xor_sync(0xffffffffu, ls0, 2);
    ls1 += __shfl_xor_sync(0xffffffffu, ls1, 1);
    ls1 += __shfl_xor_sync(0xffffffffu, ls1, 2);

    #pragma unroll
    for (int h = 0; h < 2; h++) {
        float inv = 1.f / (h ? ls1 : ls0);
        int pix = half * 128 + warp * 16 + h * 8 + lr;
        int hh = pix >> 4, ww = pix & 15;
        float* op = out + ((size_t)(jp * 16 + hh) * 128 + (ip * 16 + ww)) * 128 + m * CH;
        #pragma unroll
        for (int nc = 0; nc < 2; nc++) {
            float2 st;
            st.x = o[nc][2 * h]     * inv;
            st.y = o[nc][2 * h + 1] * inv;
            *reinterpret_cast<float2*>(op + nc * 8 + 2 * q4) = st;
        }
    }
}

extern "C" void kernel_launch(void* const* d_in, const int* in_sizes, int n_in,
                              void* d_out, int out_size) {
    const float* cv = (const float*)d_in[0];   // (1,128,128,128)
    const float* mv = (const float*)d_in[1];   // (1,2,128,128,128)
    float* out = (float*)d_out;                // (1,128,128,128)

    win_mean_kernel<<<384, 512>>>(cv, mv);
    topk_kernel<<<8, 256>>>();
    dim3 grid(P2, NUM_HEADS, 2);
    attn_kernel<<<grid, 256>>>(cv, mv, out);
}

// round 10
// speedup vs baseline: 2.6381x; 2.6319x over previous
#include <cuda_runtime.h>
#include <cuda_fp16.h>
#include <math_constants.h>
#include <cstdint>

#define NUM_HEADS 8
#define TOPK 4
#define D_MODEL 128
#define CH 16
#define P2 64
#define W2 256
#define NVIEW 2
#define SCALE_LOG2E ((float)(0.08838834764831845 * 1.4426950408889634))
#define KST 24   // kv_s row stride (halves): word=(8nt+lr)*12+q4 -> 32 distinct banks
#define VST 72   // vt_s row stride (halves): word=(4lr+q4) mod 32 -> conflict-free

__device__ float g_qwin[P2 * D_MODEL];
__device__ float g_kwin[NVIEW * P2 * D_MODEL];
__device__ int   g_ridx[P2 * TOPK];

// pack two f32 -> half2 -> 2^x
__device__ __forceinline__ uint32_t p_ex2(float lo, float hi) {
    uint32_t r;
    asm("{\n\t.reg .b32 t;\n\t"
        "cvt.rn.f16x2.f32 t, %2, %1;\n\t"
        "ex2.approx.f16x2 %0, t;\n\t}"
        : "=r"(r) : "f"(lo), "f"(hi));
    return r;
}

__device__ __forceinline__ void mma_f16(float d[4], const uint32_t a[4],
                                        uint32_t b0, uint32_t b1, const float c[4]) {
    asm volatile(
        "mma.sync.aligned.m16n8k16.row.col.f32.f16.f16.f32 "
        "{%0,%1,%2,%3}, {%4,%5,%6,%7}, {%8,%9}, {%10,%11,%12,%13};"
        : "=f"(d[0]), "=f"(d[1]), "=f"(d[2]), "=f"(d[3])
        : "r"(a[0]), "r"(a[1]), "r"(a[2]), "r"(a[3]), "r"(b0), "r"(b1),
          "f"(c[0]), "f"(c[1]), "f"(c[2]), "f"(c[3]));
}

// ---------------------------------------------------------------------------
// Kernel 1: window means (float4 loads, 1024 threads) — round-5 exact
// ---------------------------------------------------------------------------
__global__ void win_mean_kernel(const float* __restrict__ cv,
                                const float* __restrict__ mv) {
    __shared__ float4 red[1024];
    int b = blockIdx.x;
    int t = threadIdx.x;
    int c4 = t & 31;
    int part = t >> 5;
    const float* src;
    float* dst;
    int p;
    if (b < P2) {
        p = b; src = cv; dst = g_qwin + p * D_MODEL;
    } else {
        int vp = b - P2;
        int v = vp >> 6; p = vp & 63;
        src = mv + (size_t)v * 128 * 128 * 128;
        dst = g_kwin + vp * D_MODEL;
    }
    int jp = p >> 3, ip = p & 7;
    int y0 = jp * 16, x0 = ip * 16;
    float4 s = make_float4(0.f, 0.f, 0.f, 0.f);
    #pragma unroll
    for (int u = 0; u < 8; u++) {
        int pix = part * 8 + u;
        int hh = pix >> 4, ww = pix & 15;
        float4 x = *(reinterpret_cast<const float4*>(
            src + ((size_t)(y0 + hh) * 128 + (x0 + ww)) * 128) + c4);
        s.x += x.x; s.y += x.y; s.z += x.z; s.w += x.w;
    }
    red[t] = s;
    __syncthreads();
    if (t < 32) {
        float4 acc = make_float4(0.f, 0.f, 0.f, 0.f);
        #pragma unroll
        for (int k = 0; k < 32; k++) {
            float4 x = red[k * 32 + t];
            acc.x += x.x; acc.y += x.y; acc.z += x.z; acc.w += x.w;
        }
        const float inv = 1.f / 256.f;
        acc.x *= inv; acc.y *= inv; acc.z *= inv; acc.w *= inv;
        reinterpret_cast<float4*>(dst)[t] = acc;
    }
}

// ---------------------------------------------------------------------------
// Kernel 2: routing + top-4 — round-5 structure; ONLY change: float4 loads
// ---------------------------------------------------------------------------
__global__ void topk_kernel() {
    __shared__ __align__(16) float q_s[8 * D_MODEL];
    int t = threadIdx.x;
    int warp = t >> 5, lane = t & 31;
    int row = blockIdx.x * 8 + warp;

    for (int i = t; i < 8 * D_MODEL; i += 256)
        q_s[i] = g_qwin[blockIdx.x * 8 * D_MODEL + i];
    __syncthreads();

    float v[4]; int id[4];
    const float4* qr4 = reinterpret_cast<const float4*>(q_s + warp * D_MODEL);
    #pragma unroll
    for (int kloc = 0; kloc < 4; kloc++) {
        int j = lane * 4 + kloc;
        const float4* kr4 = reinterpret_cast<const float4*>(g_kwin + j * D_MODEL);
        float s = 0.f;
        #pragma unroll 8
        for (int c4 = 0; c4 < D_MODEL / 4; c4++) {
            float4 q = qr4[c4];
            float4 k = kr4[c4];
            s += q.x * k.x + q.y * k.y + q.z * k.z + q.w * k.w;
        }
        v[kloc] = s; id[kloc] = j;
    }
    #pragma unroll
    for (int r = 0; r < TOPK; r++) {
        float bv = v[0]; int bi = id[0];
        #pragma unroll
        for (int kloc = 1; kloc < 4; kloc++)
            if (v[kloc] > bv || (v[kloc] == bv && id[kloc] < bi)) { bv = v[kloc]; bi = id[kloc]; }
        float wv = bv; int wi = bi;
        #pragma unroll
        for (int off = 16; off; off >>= 1) {
            float ov = __shfl_down_sync(0xffffffffu, wv, off);
            int   oi = __shfl_down_sync(0xffffffffu, wi, off);
            if (ov > wv || (ov == wv && oi < wi)) { wv = ov; wi = oi; }
        }
        wi = __shfl_sync(0xffffffffu, wi, 0);
        if ((wi >> 2) == lane) v[wi & 3] = -CUDART_INF_F;
        if (lane == 0) g_ridx[row * TOPK + r] = wi;
    }
}

// ---------------------------------------------------------------------------
// Kernel 3: round-5 exact. fp16 attention, no-max softmax, f32-accum QK.
// Grid (64,8,2), 256 threads / 8 warps x 16 q-rows, 2 CTAs per SM,
// 16 chunks of 64 kv rows, double-buffered.
// ---------------------------------------------------------------------------
__global__ void __launch_bounds__(256, 2)
attn_kernel(const float* __restrict__ cv,
            const float* __restrict__ mv,
            float* __restrict__ out) {
    int p = blockIdx.x;      // window
    int m = blockIdx.y;      // head
    int half = blockIdx.z;   // which 128 query rows
    int t = threadIdx.x;
    int warp = t >> 5, lane = t & 31;
    int lr = lane >> 2, q4 = lane & 3;

    __shared__ __half q_s[128 * CH];         // 4 KB
    __shared__ __half kv_s[2][64 * KST];     // 2 x 3 KB (k-major, padded)
    __shared__ __half vt_s[2][CH * VST];     // 2 x 2.25 KB (transposed)
    __shared__ int sel_s[TOPK];

    int jp = p >> 3, ip = p & 7;

    // ---- stage Q: local row t = window pixel half*128+t, scaled ----
    if (t < 128) {
        int pix = half * 128 + t;
        int hh = pix >> 4, ww = pix & 15;
        const float4* gp = reinterpret_cast<const float4*>(
            cv + ((size_t)(jp * 16 + hh) * 128 + (ip * 16 + ww)) * 128 + m * CH);
        float4 x0 = gp[0], x1 = gp[1], x2 = gp[2], x3 = gp[3];
        const float s = SCALE_LOG2E;
        __half2* dst = reinterpret_cast<__half2*>(q_s + t * CH);
        dst[0] = __floats2half2_rn(x0.x * s, x0.y * s);
        dst[1] = __floats2half2_rn(x0.z * s, x0.w * s);
        dst[2] = __floats2half2_rn(x1.x * s, x1.y * s);
        dst[3] = __floats2half2_rn(x1.z * s, x1.w * s);
        dst[4] = __floats2half2_rn(x2.x * s, x2.y * s);
        dst[5] = __floats2half2_rn(x2.z * s, x2.w * s);
        dst[6] = __floats2half2_rn(x3.x * s, x3.y * s);
        dst[7] = __floats2half2_rn(x3.z * s, x3.w * s);
    }
    if (t < TOPK) sel_s[t] = g_ridx[p * TOPK + t];
    __syncthreads();

    int sel[TOPK];
    #pragma unroll
    for (int k = 0; k < TOPK; k++) sel[k] = sel_s[k];

    // ---- Q a-frag ----
    uint32_t qa[4];
    {
        int r0 = warp * 16 + lr;
        qa[0] = *reinterpret_cast<const uint32_t*>(q_s + r0 * CH + 2 * q4);
        qa[1] = *reinterpret_cast<const uint32_t*>(q_s + (r0 + 8) * CH + 2 * q4);
        qa[2] = *reinterpret_cast<const uint32_t*>(q_s + r0 * CH + 8 + 2 * q4);
        qa[3] = *reinterpret_cast<const uint32_t*>(q_s + (r0 + 8) * CH + 8 + 2 * q4);
    }

    // staging roles: 256 threads = 32 pixel-slots x 8 ch-pairs; 2 pixels each
    int pixg = t >> 3;
    int cg   = t & 7;

    float o[2][4];
    float ls0 = 0.f, ls1 = 0.f;
    #pragma unroll
    for (int u = 0; u < 4; u++) { o[0][u] = 0.f; o[1][u] = 0.f; }

    auto ldchunk = [&](int c, float2& fa, float2& fb) {
        int s = sel[c >> 2];
        int jv = (s & 63) >> 3, iv = s & 7;
        const float* base = mv + (size_t)(s >> 6) * 128 * 128 * 128;
        int p0 = (c & 3) * 64 + pixg;
        int p1 = p0 + 32;
        int y0v = jv * 16 + (p0 >> 4), x0v = iv * 16 + (p0 & 15);
        int y1v = jv * 16 + (p1 >> 4), x1v = iv * 16 + (p1 & 15);
        fa = *reinterpret_cast<const float2*>(
            base + ((size_t)y0v * 128 + x0v) * 128 + m * CH + cg * 2);
        fb = *reinterpret_cast<const float2*>(
            base + ((size_t)y1v * 128 + x1v) * 128 + m * CH + cg * 2);
    };
    auto stchunk = [&](int buf, float2 fa, float2 fb) {
        __half2 ha = __floats2half2_rn(fa.x, fa.y);
        __half2 hb = __floats2half2_rn(fb.x, fb.y);
        *reinterpret_cast<__half2*>(kv_s[buf] + pixg * KST + cg * 2) = ha;
        *reinterpret_cast<__half2*>(kv_s[buf] + (pixg + 32) * KST + cg * 2) = hb;
        vt_s[buf][(cg * 2) * VST + pixg]          = __low2half(ha);
        vt_s[buf][(cg * 2 + 1) * VST + pixg]      = __high2half(ha);
        vt_s[buf][(cg * 2) * VST + pixg + 32]     = __low2half(hb);
        vt_s[buf][(cg * 2 + 1) * VST + pixg + 32] = __high2half(hb);
    };

    {
        float2 fa, fb;
        ldchunk(0, fa, fb);
        stchunk(0, fa, fb);
    }
    __syncthreads();

    for (int c = 0; c < 16; c++) {
        int cur = c & 1;
        float2 nfa, nfb;
        if (c + 1 < 16) ldchunk(c + 1, nfa, nfb);   // LDG overlaps compute

        // ---- S = Q K^T (f32 accum, base-2 log domain) ----
        float sc[8][4];
        #pragma unroll
        for (int nt = 0; nt < 8; nt++)
            #pragma unroll
            for (int u = 0; u < 4; u++) sc[nt][u] = 0.f;
        #pragma unroll
        for (int nt = 0; nt < 8; nt++) {
            const __half* kr = kv_s[cur] + (nt * 8 + lr) * KST;
            uint32_t b0 = *reinterpret_cast<const uint32_t*>(kr + 2 * q4);
            uint32_t b1 = *reinterpret_cast<const uint32_t*>(kr + 8 + 2 * q4);
            mma_f16(sc[nt], qa, b0, b1, sc[nt]);
        }

        // ---- P = 2^S packed into fp16 a-frags ----
        uint32_t pa[4][4];
        #pragma unroll
        for (int ks = 0; ks < 4; ks++) {
            pa[ks][0] = p_ex2(sc[2 * ks][0],     sc[2 * ks][1]);
            pa[ks][1] = p_ex2(sc[2 * ks][2],     sc[2 * ks][3]);
            pa[ks][2] = p_ex2(sc[2 * ks + 1][0], sc[2 * ks + 1][1]);
            pa[ks][3] = p_ex2(sc[2 * ks + 1][2], sc[2 * ks + 1][3]);
        }

        // ---- row sums on scalar pipes (one f16 add level, then f32) ----
        #pragma unroll
        for (int ks = 0; ks < 4; ks++) {
            __half2 w0 = __hadd2(*reinterpret_cast<__half2*>(&pa[ks][0]),
                                 *reinterpret_cast<__half2*>(&pa[ks][2]));
            __half2 w1 = __hadd2(*reinterpret_cast<__half2*>(&pa[ks][1]),
                                 *reinterpret_cast<__half2*>(&pa[ks][3]));
            float2 f0 = __half22float2(w0);
            float2 f1 = __half22float2(w1);
            ls0 += f0.x + f0.y;
            ls1 += f1.x + f1.y;
        }

        // ---- O += P V ----
        #pragma unroll
        for (int ks = 0; ks < 4; ks++) {
            #pragma unroll
            for (int nc = 0; nc < 2; nc++) {
                const __half* vr = vt_s[cur] + (nc * 8 + lr) * VST + ks * 16;
                uint32_t b0 = *reinterpret_cast<const uint32_t*>(vr + 2 * q4);
                uint32_t b1 = *reinterpret_cast<const uint32_t*>(vr + 8 + 2 * q4);
                mma_f16(o[nc], pa[ks], b0, b1, o[nc]);
            }
        }

        if (c + 1 < 16) stchunk((c + 1) & 1, nfa, nfb);
        __syncthreads();
    }

    // ---- epilogue: quad-reduce row sums, normalize, store ----
    ls0 += __shfl_xor_sync(0xffffffffu, ls0, 1);
    ls0 += __shfl_xor_sync(0xffffffffu, ls0, 2);
    ls1 += __shfl_xor_sync(0xffffffffu, ls1, 1);
    ls1 += __shfl_xor_sync(0xffffffffu, ls1, 2);

    #pragma unroll
    for (int h = 0; h < 2; h++) {
        float inv = 1.f / (h ? ls1 : ls0);
        int pix = half * 128 + warp * 16 + h * 8 + lr;
        int hh = pix >> 4, ww = pix & 15;
        float* op = out + ((size_t)(jp * 16 + hh) * 128 + (ip * 16 + ww)) * 128 + m * CH;
        #pragma unroll
        for (int nc = 0; nc < 2; nc++) {
            float2 st;
            st.x = o[nc][2 * h]     * inv;
            st.y = o[nc][2 * h + 1] * inv;
            *reinterpret_cast<float2*>(op + nc * 8 + 2 * q4) = st;
        }
    }
}

extern "C" void kernel_launch(void* const* d_in, const int* in_sizes, int n_in,
                              void* d_out, int out_size) {
    const float* cv = (const float*)d_in[0];   // (1,128,128,128)
    const float* mv = (const float*)d_in[1];   // (1,2,128,128,128)
    float* out = (float*)d_out;                // (1,128,128,128)

    win_mean_kernel<<<192, 1024>>>(cv, mv);
    topk_kernel<<<8, 256>>>();
    dim3 grid(P2, NUM_HEADS, 2);
    attn_kernel<<<grid, 256>>>(cv, mv, out);
}

// round 11
// speedup vs baseline: 2.6752x; 1.0141x over previous
#include <cuda_runtime.h>
#include <cuda_fp16.h>
#include <math_constants.h>
#include <cstdint>

#define NUM_HEADS 8
#define TOPK 4
#define D_MODEL 128
#define CH 16
#define P2 64
#define W2 256
#define NVIEW 2
#define SCALE_LOG2E ((float)(0.08838834764831845 * 1.4426950408889634))
#define KST 24   // kv_s row stride (halves): word=(8nt+lr)*12+q4 -> 32 distinct banks
#define VST 72   // vt_s row stride (halves): word=(4lr+q4) mod 32 -> conflict-free

__device__ float g_qwin[P2 * D_MODEL];
__device__ float g_kwin[NVIEW * P2 * D_MODEL];
__device__ int   g_ridx[P2 * TOPK];

// pack two f32 -> half2 -> 2^x
__device__ __forceinline__ uint32_t p_ex2(float lo, float hi) {
    uint32_t r;
    asm("{\n\t.reg .b32 t;\n\t"
        "cvt.rn.f16x2.f32 t, %2, %1;\n\t"
        "ex2.approx.f16x2 %0, t;\n\t}"
        : "=r"(r) : "f"(lo), "f"(hi));
    return r;
}

__device__ __forceinline__ void mma_f16(float d[4], const uint32_t a[4],
                                        uint32_t b0, uint32_t b1, const float c[4]) {
    asm volatile(
        "mma.sync.aligned.m16n8k16.row.col.f32.f16.f16.f32 "
        "{%0,%1,%2,%3}, {%4,%5,%6,%7}, {%8,%9}, {%10,%11,%12,%13};"
        : "=f"(d[0]), "=f"(d[1]), "=f"(d[2]), "=f"(d[3])
        : "r"(a[0]), "r"(a[1]), "r"(a[2]), "r"(a[3]), "r"(b0), "r"(b1),
          "f"(c[0]), "f"(c[1]), "f"(c[2]), "f"(c[3]));
}

// ---------------------------------------------------------------------------
// Kernel 1: window means (float4 loads, 1024 threads) — unchanged (validated)
// ---------------------------------------------------------------------------
__global__ void win_mean_kernel(const float* __restrict__ cv,
                                const float* __restrict__ mv) {
    __shared__ float4 red[1024];
    int b = blockIdx.x;
    int t = threadIdx.x;
    int c4 = t & 31;
    int part = t >> 5;
    const float* src;
    float* dst;
    int p;
    if (b < P2) {
        p = b; src = cv; dst = g_qwin + p * D_MODEL;
    } else {
        int vp = b - P2;
        int v = vp >> 6; p = vp & 63;
        src = mv + (size_t)v * 128 * 128 * 128;
        dst = g_kwin + vp * D_MODEL;
    }
    int jp = p >> 3, ip = p & 7;
    int y0 = jp * 16, x0 = ip * 16;
    float4 s = make_float4(0.f, 0.f, 0.f, 0.f);
    #pragma unroll
    for (int u = 0; u < 8; u++) {
        int pix = part * 8 + u;
        int hh = pix >> 4, ww = pix & 15;
        float4 x = *(reinterpret_cast<const float4*>(
            src + ((size_t)(y0 + hh) * 128 + (x0 + ww)) * 128) + c4);
        s.x += x.x; s.y += x.y; s.z += x.z; s.w += x.w;
    }
    red[t] = s;
    __syncthreads();
    if (t < 32) {
        float4 acc = make_float4(0.f, 0.f, 0.f, 0.f);
        #pragma unroll
        for (int k = 0; k < 32; k++) {
            float4 x = red[k * 32 + t];
            acc.x += x.x; acc.y += x.y; acc.z += x.z; acc.w += x.w;
        }
        const float inv = 1.f / 256.f;
        acc.x *= inv; acc.y *= inv; acc.z *= inv; acc.w *= inv;
        reinterpret_cast<float4*>(dst)[t] = acc;
    }
}

// ---------------------------------------------------------------------------
// Kernel 2: routing + top-4, float4 loads — unchanged (validated)
// ---------------------------------------------------------------------------
__global__ void topk_kernel() {
    __shared__ __align__(16) float q_s[8 * D_MODEL];
    int t = threadIdx.x;
    int warp = t >> 5, lane = t & 31;
    int row = blockIdx.x * 8 + warp;

    for (int i = t; i < 8 * D_MODEL; i += 256)
        q_s[i] = g_qwin[blockIdx.x * 8 * D_MODEL + i];
    __syncthreads();

    float v[4]; int id[4];
    const float4* qr4 = reinterpret_cast<const float4*>(q_s + warp * D_MODEL);
    #pragma unroll
    for (int kloc = 0; kloc < 4; kloc++) {
        int j = lane * 4 + kloc;
        const float4* kr4 = reinterpret_cast<const float4*>(g_kwin + j * D_MODEL);
        float s = 0.f;
        #pragma unroll 8
        for (int c4 = 0; c4 < D_MODEL / 4; c4++) {
            float4 q = qr4[c4];
            float4 k = kr4[c4];
            s += q.x * k.x + q.y * k.y + q.z * k.z + q.w * k.w;
        }
        v[kloc] = s; id[kloc] = j;
    }
    #pragma unroll
    for (int r = 0; r < TOPK; r++) {
        float bv = v[0]; int bi = id[0];
        #pragma unroll
        for (int kloc = 1; kloc < 4; kloc++)
            if (v[kloc] > bv || (v[kloc] == bv && id[kloc] < bi)) { bv = v[kloc]; bi = id[kloc]; }
        float wv = bv; int wi = bi;
        #pragma unroll
        for (int off = 16; off; off >>= 1) {
            float ov = __shfl_down_sync(0xffffffffu, wv, off);
            int   oi = __shfl_down_sync(0xffffffffu, wi, off);
            if (ov > wv || (ov == wv && oi < wi)) { wv = ov; wi = oi; }
        }
        wi = __shfl_sync(0xffffffffu, wi, 0);
        if ((wi >> 2) == lane) v[wi & 3] = -CUDART_INF_F;
        if (lane == 0) g_ridx[row * TOPK + r] = wi;
    }
}

// ---------------------------------------------------------------------------
// Kernel 3: fp16 attention, no-max softmax, f32-accum QK.
// SINGLE CHANGE vs 66.9us baseline: occupancy 2 -> 3 (85-reg cap), enabled by
// splitting QK into two 4-nt passes (peak live S regs 32 -> 16).
// ---------------------------------------------------------------------------
__global__ void __launch_bounds__(256, 3)
attn_kernel(const float* __restrict__ cv,
            const float* __restrict__ mv,
            float* __restrict__ out) {
    int p = blockIdx.x;      // window
    int m = blockIdx.y;      // head
    int half = blockIdx.z;   // which 128 query rows
    int t = threadIdx.x;
    int warp = t >> 5, lane = t & 31;
    int lr = lane >> 2, q4 = lane & 3;

    __shared__ __half q_s[128 * CH];         // 4 KB
    __shared__ __half kv_s[2][64 * KST];     // 2 x 3 KB (k-major, padded)
    __shared__ __half vt_s[2][CH * VST];     // 2 x 2.25 KB (transposed)
    __shared__ int sel_s[TOPK];

    int jp = p >> 3, ip = p & 7;

    // ---- stage Q ----
    if (t < 128) {
        int pix = half * 128 + t;
        int hh = pix >> 4, ww = pix & 15;
        const float4* gp = reinterpret_cast<const float4*>(
            cv + ((size_t)(jp * 16 + hh) * 128 + (ip * 16 + ww)) * 128 + m * CH);
        float4 x0 = gp[0], x1 = gp[1], x2 = gp[2], x3 = gp[3];
        const float s = SCALE_LOG2E;
        __half2* dst = reinterpret_cast<__half2*>(q_s + t * CH);
        dst[0] = __floats2half2_rn(x0.x * s, x0.y * s);
        dst[1] = __floats2half2_rn(x0.z * s, x0.w * s);
        dst[2] = __floats2half2_rn(x1.x * s, x1.y * s);
        dst[3] = __floats2half2_rn(x1.z * s, x1.w * s);
        dst[4] = __floats2half2_rn(x2.x * s, x2.y * s);
        dst[5] = __floats2half2_rn(x2.z * s, x2.w * s);
        dst[6] = __floats2half2_rn(x3.x * s, x3.y * s);
        dst[7] = __floats2half2_rn(x3.z * s, x3.w * s);
    }
    if (t < TOPK) sel_s[t] = g_ridx[p * TOPK + t];
    __syncthreads();

    int sel[TOPK];
    #pragma unroll
    for (int k = 0; k < TOPK; k++) sel[k] = sel_s[k];

    // ---- Q a-frag ----
    uint32_t qa[4];
    {
        int r0 = warp * 16 + lr;
        qa[0] = *reinterpret_cast<const uint32_t*>(q_s + r0 * CH + 2 * q4);
        qa[1] = *reinterpret_cast<const uint32_t*>(q_s + (r0 + 8) * CH + 2 * q4);
        qa[2] = *reinterpret_cast<const uint32_t*>(q_s + r0 * CH + 8 + 2 * q4);
        qa[3] = *reinterpret_cast<const uint32_t*>(q_s + (r0 + 8) * CH + 8 + 2 * q4);
    }

    // staging roles: 256 threads = 32 pixel-slots x 8 ch-pairs; 2 pixels each
    int pixg = t >> 3;
    int cg   = t & 7;

    float o[2][4];
    float ls0 = 0.f, ls1 = 0.f;
    #pragma unroll
    for (int u = 0; u < 4; u++) { o[0][u] = 0.f; o[1][u] = 0.f; }

    auto ldchunk = [&](int c, float2& fa, float2& fb) {
        int s = sel[c >> 2];
        int jv = (s & 63) >> 3, iv = s & 7;
        const float* base = mv + (size_t)(s >> 6) * 128 * 128 * 128;
        int p0 = (c & 3) * 64 + pixg;
        int p1 = p0 + 32;
        int y0v = jv * 16 + (p0 >> 4), x0v = iv * 16 + (p0 & 15);
        int y1v = jv * 16 + (p1 >> 4), x1v = iv * 16 + (p1 & 15);
        fa = *reinterpret_cast<const float2*>(
            base + ((size_t)y0v * 128 + x0v) * 128 + m * CH + cg * 2);
        fb = *reinterpret_cast<const float2*>(
            base + ((size_t)y1v * 128 + x1v) * 128 + m * CH + cg * 2);
    };
    auto stchunk = [&](int buf, float2 fa, float2 fb) {
        __half2 ha = __floats2half2_rn(fa.x, fa.y);
        __half2 hb = __floats2half2_rn(fb.x, fb.y);
        *reinterpret_cast<__half2*>(kv_s[buf] + pixg * KST + cg * 2) = ha;
        *reinterpret_cast<__half2*>(kv_s[buf] + (pixg + 32) * KST + cg * 2) = hb;
        vt_s[buf][(cg * 2) * VST + pixg]          = __low2half(ha);
        vt_s[buf][(cg * 2 + 1) * VST + pixg]      = __high2half(ha);
        vt_s[buf][(cg * 2) * VST + pixg + 32]     = __low2half(hb);
        vt_s[buf][(cg * 2 + 1) * VST + pixg + 32] = __high2half(hb);
    };

    {
        float2 fa, fb;
        ldchunk(0, fa, fb);
        stchunk(0, fa, fb);
    }
    __syncthreads();

    for (int c = 0; c < 16; c++) {
        int cur = c & 1;
        float2 nfa, nfb;
        if (c + 1 < 16) ldchunk(c + 1, nfa, nfb);   // LDG overlaps compute

        // ---- S = Q K^T (f32 accum) in two 4-nt passes; P = 2^S -> pa ----
        uint32_t pa[4][4];
        #pragma unroll
        for (int g = 0; g < 2; g++) {
            float sc[4][4];
            #pragma unroll
            for (int nt = 0; nt < 4; nt++)
                #pragma unroll
                for (int u = 0; u < 4; u++) sc[nt][u] = 0.f;
            #pragma unroll
            for (int nt = 0; nt < 4; nt++) {
                int ntg = g * 4 + nt;
                const __half* kr = kv_s[cur] + (ntg * 8 + lr) * KST;
                uint32_t b0 = *reinterpret_cast<const uint32_t*>(kr + 2 * q4);
                uint32_t b1 = *reinterpret_cast<const uint32_t*>(kr + 8 + 2 * q4);
                mma_f16(sc[nt], qa, b0, b1, sc[nt]);
            }
            #pragma unroll
            for (int ks = 0; ks < 2; ks++) {
                int kg = g * 2 + ks;
                pa[kg][0] = p_ex2(sc[2 * ks][0],     sc[2 * ks][1]);
                pa[kg][1] = p_ex2(sc[2 * ks][2],     sc[2 * ks][3]);
                pa[kg][2] = p_ex2(sc[2 * ks + 1][0], sc[2 * ks + 1][1]);
                pa[kg][3] = p_ex2(sc[2 * ks + 1][2], sc[2 * ks + 1][3]);
            }
        }

        // ---- row sums on scalar pipes (one f16 add level, then f32) ----
        #pragma unroll
        for (int ks = 0; ks < 4; ks++) {
            __half2 w0 = __hadd2(*reinterpret_cast<__half2*>(&pa[ks][0]),
                                 *reinterpret_cast<__half2*>(&pa[ks][2]));
            __half2 w1 = __hadd2(*reinterpret_cast<__half2*>(&pa[ks][1]),
                                 *reinterpret_cast<__half2*>(&pa[ks][3]));
            float2 f0 = __half22float2(w0);
            float2 f1 = __half22float2(w1);
            ls0 += f0.x + f0.y;
            ls1 += f1.x + f1.y;
        }

        // ---- O += P V ----
        #pragma unroll
        for (int ks = 0; ks < 4; ks++) {
            #pragma unroll
            for (int nc = 0; nc < 2; nc++) {
                const __half* vr = vt_s[cur] + (nc * 8 + lr) * VST + ks * 16;
                uint32_t b0 = *reinterpret_cast<const uint32_t*>(vr + 2 * q4);
                uint32_t b1 = *reinterpret_cast<const uint32_t*>(vr + 8 + 2 * q4);
                mma_f16(o[nc], pa[ks], b0, b1, o[nc]);
            }
        }

        if (c + 1 < 16) stchunk((c + 1) & 1, nfa, nfb);
        __syncthreads();
    }

    // ---- epilogue: quad-reduce row sums, normalize, store ----
    ls0 += __shfl_xor_sync(0xffffffffu, ls0, 1);
    ls0 += __shfl_xor_sync(0xffffffffu, ls0, 2);
    ls1 += __shfl_xor_sync(0xffffffffu, ls1, 1);
    ls1 += __shfl_xor_sync(0xffffffffu, ls1, 2);

    #pragma unroll
    for (int h = 0; h < 2; h++) {
        float inv = 1.f / (h ? ls1 : ls0);
        int pix = half * 128 + warp * 16 + h * 8 + lr;
        int hh = pix >> 4, ww = pix & 15;
        float* op = out + ((size_t)(jp * 16 + hh) * 128 + (ip * 16 + ww)) * 128 + m * CH;
        #pragma unroll
        for (int nc = 0; nc < 2; nc++) {
            float2 st;
            st.x = o[nc][2 * h]     * inv;
            st.y = o[nc][2 * h + 1] * inv;
            *reinterpret_cast<float2*>(op + nc * 8 + 2 * q4) = st;
        }
    }
}

extern "C" void kernel_launch(void* const* d_in, const int* in_sizes, int n_in,
                              void* d_out, int out_size) {
    const float* cv = (const float*)d_in[0];   // (1,128,128,128)
    const float* mv = (const float*)d_in[1];   // (1,2,128,128,128)
    float* out = (float*)d_out;                // (1,128,128,128)

    win_mean_kernel<<<192, 1024>>>(cv, mv);
    topk_kernel<<<8, 256>>>();
    dim3 grid(P2, NUM_HEADS, 2);
    attn_kernel<<<grid, 256>>>(cv, mv, out);
}

// round 12
// speedup vs baseline: 3.3984x; 1.2703x over previous
#include <cuda_runtime.h>
#include <cuda_fp16.h>
#include <math_constants.h>
#include <cstdint>

#define NUM_HEADS 8
#define TOPK 4
#define D_MODEL 128
#define CH 16
#define P2 64
#define W2 256
#define NVIEW 2
#define SCALE_LOG2E ((float)(0.08838834764831845 * 1.4426950408889634))
#define KST 24   // kv_s row stride (halves): word=(8nt+lr)*12+q4 -> 32 distinct banks
#define VST 72   // vt_s row stride (halves): word=(4lr+q4) mod 32 -> conflict-free

__device__ float g_qwin[P2 * D_MODEL];
__device__ float g_kwinT[D_MODEL * NVIEW * P2];   // [channel][view*win] transposed
__device__ int   g_ridx[P2 * TOPK];

// pack two f32 -> half2 -> 2^x
__device__ __forceinline__ uint32_t p_ex2(float lo, float hi) {
    uint32_t r;
    asm("{\n\t.reg .b32 t;\n\t"
        "cvt.rn.f16x2.f32 t, %2, %1;\n\t"
        "ex2.approx.f16x2 %0, t;\n\t}"
        : "=r"(r) : "f"(lo), "f"(hi));
    return r;
}

__device__ __forceinline__ void mma_f16(float d[4], const uint32_t a[4],
                                        uint32_t b0, uint32_t b1, const float c[4]) {
    asm volatile(
        "mma.sync.aligned.m16n8k16.row.col.f32.f16.f16.f32 "
        "{%0,%1,%2,%3}, {%4,%5,%6,%7}, {%8,%9}, {%10,%11,%12,%13};"
        : "=f"(d[0]), "=f"(d[1]), "=f"(d[2]), "=f"(d[3])
        : "r"(a[0]), "r"(a[1]), "r"(a[2]), "r"(a[3]), "r"(b0), "r"(b1),
          "f"(c[0]), "f"(c[1]), "f"(c[2]), "f"(c[3]));
}

// ---------------------------------------------------------------------------
// Kernel 1: window means (float4 loads, 1024 threads). k output TRANSPOSED.
// ---------------------------------------------------------------------------
__global__ void win_mean_kernel(const float* __restrict__ cv,
                                const float* __restrict__ mv) {
    __shared__ float4 red[1024];
    int b = blockIdx.x;
    int t = threadIdx.x;
    int c4 = t & 31;
    int part = t >> 5;
    const float* src;
    int p;
    bool is_q = (b < P2);
    int widx = 0;
    if (is_q) {
        p = b; src = cv;
    } else {
        int vp = b - P2;
        int v = vp >> 6; p = vp & 63;
        src = mv + (size_t)v * 128 * 128 * 128;
        widx = vp;
    }
    int jp = p >> 3, ip = p & 7;
    int y0 = jp * 16, x0 = ip * 16;
    float4 s = make_float4(0.f, 0.f, 0.f, 0.f);
    #pragma unroll
    for (int u = 0; u < 8; u++) {
        int pix = part * 8 + u;
        int hh = pix >> 4, ww = pix & 15;
        float4 x = *(reinterpret_cast<const float4*>(
            src + ((size_t)(y0 + hh) * 128 + (x0 + ww)) * 128) + c4);
        s.x += x.x; s.y += x.y; s.z += x.z; s.w += x.w;
    }
    red[t] = s;
    __syncthreads();
    if (t < 32) {
        float4 acc = make_float4(0.f, 0.f, 0.f, 0.f);
        #pragma unroll
        for (int k = 0; k < 32; k++) {
            float4 x = red[k * 32 + t];
            acc.x += x.x; acc.y += x.y; acc.z += x.z; acc.w += x.w;
        }
        const float inv = 1.f / 256.f;
        acc.x *= inv; acc.y *= inv; acc.z *= inv; acc.w *= inv;
        if (is_q) {
            reinterpret_cast<float4*>(g_qwin + p * D_MODEL)[t] = acc;
        } else {
            g_kwinT[(4 * t + 0) * 128 + widx] = acc.x;
            g_kwinT[(4 * t + 1) * 128 + widx] = acc.y;
            g_kwinT[(4 * t + 2) * 128 + widx] = acc.z;
            g_kwinT[(4 * t + 3) * 128 + widx] = acc.w;
        }
    }
}

// ---------------------------------------------------------------------------
// Kernel 2: routing + top-4. 64 blocks (one per q-row) x 128 threads (one per
// key). kT reads fully coalesced and L2-resident.
// ---------------------------------------------------------------------------
__global__ void topk_kernel() {
    __shared__ float q_s[D_MODEL];
    __shared__ float logit[128];
    int row = blockIdx.x;
    int t = threadIdx.x;

    q_s[t] = g_qwin[row * D_MODEL + t];
    __syncthreads();

    float s = 0.f;
    #pragma unroll 16
    for (int c = 0; c < D_MODEL; c++)
        s += q_s[c] * g_kwinT[c * 128 + t];
    logit[t] = s;
    __syncthreads();

    if (t < 32) {
        float v[4]; int id[4];
        #pragma unroll
        for (int kloc = 0; kloc < 4; kloc++) {
            int j = t * 4 + kloc;
            v[kloc] = logit[j]; id[kloc] = j;
        }
        #pragma unroll
        for (int r = 0; r < TOPK; r++) {
            float bv = v[0]; int bi = id[0];
            #pragma unroll
            for (int kloc = 1; kloc < 4; kloc++)
                if (v[kloc] > bv || (v[kloc] == bv && id[kloc] < bi)) { bv = v[kloc]; bi = id[kloc]; }
            float wv = bv; int wi = bi;
            #pragma unroll
            for (int off = 16; off; off >>= 1) {
                float ov = __shfl_down_sync(0xffffffffu, wv, off);
                int   oi = __shfl_down_sync(0xffffffffu, wi, off);
                if (ov > wv || (ov == wv && oi < wi)) { wv = ov; wi = oi; }
            }
            wi = __shfl_sync(0xffffffffu, wi, 0);
            if ((wi >> 2) == t) v[wi & 3] = -CUDART_INF_F;
            if (t == 0) g_ridx[row * TOPK + r] = wi;
        }
    }
}

// ---------------------------------------------------------------------------
// Kernel 3: fp16 attention, no-max softmax, f32-accum QK, split QK passes,
// occ 3. Change vs 66.0us baseline: row sums moved AFTER the PV MMAs.
// ---------------------------------------------------------------------------
__global__ void __launch_bounds__(256, 3)
attn_kernel(const float* __restrict__ cv,
            const float* __restrict__ mv,
            float* __restrict__ out) {
    int p = blockIdx.x;      // window
    int m = blockIdx.y;      // head
    int half = blockIdx.z;   // which 128 query rows
    int t = threadIdx.x;
    int warp = t >> 5, lane = t & 31;
    int lr = lane >> 2, q4 = lane & 3;

    __shared__ __half q_s[128 * CH];         // 4 KB
    __shared__ __half kv_s[2][64 * KST];     // 2 x 3 KB (k-major, padded)
    __shared__ __half vt_s[2][CH * VST];     // 2 x 2.25 KB (transposed)
    __shared__ int sel_s[TOPK];

    int jp = p >> 3, ip = p & 7;

    // ---- stage Q ----
    if (t < 128) {
        int pix = half * 128 + t;
        int hh = pix >> 4, ww = pix & 15;
        const float4* gp = reinterpret_cast<const float4*>(
            cv + ((size_t)(jp * 16 + hh) * 128 + (ip * 16 + ww)) * 128 + m * CH);
        float4 x0 = gp[0], x1 = gp[1], x2 = gp[2], x3 = gp[3];
        const float s = SCALE_LOG2E;
        __half2* dst = reinterpret_cast<__half2*>(q_s + t * CH);
        dst[0] = __floats2half2_rn(x0.x * s, x0.y * s);
        dst[1] = __floats2half2_rn(x0.z * s, x0.w * s);
        dst[2] = __floats2half2_rn(x1.x * s, x1.y * s);
        dst[3] = __floats2half2_rn(x1.z * s, x1.w * s);
        dst[4] = __floats2half2_rn(x2.x * s, x2.y * s);
        dst[5] = __floats2half2_rn(x2.z * s, x2.w * s);
        dst[6] = __floats2half2_rn(x3.x * s, x3.y * s);
        dst[7] = __floats2half2_rn(x3.z * s, x3.w * s);
    }
    if (t < TOPK) sel_s[t] = g_ridx[p * TOPK + t];
    __syncthreads();

    int sel[TOPK];
    #pragma unroll
    for (int k = 0; k < TOPK; k++) sel[k] = sel_s[k];

    // ---- Q a-frag ----
    uint32_t qa[4];
    {
        int r0 = warp * 16 + lr;
        qa[0] = *reinterpret_cast<const uint32_t*>(q_s + r0 * CH + 2 * q4);
        qa[1] = *reinterpret_cast<const uint32_t*>(q_s + (r0 + 8) * CH + 2 * q4);
        qa[2] = *reinterpret_cast<const uint32_t*>(q_s + r0 * CH + 8 + 2 * q4);
        qa[3] = *reinterpret_cast<const uint32_t*>(q_s + (r0 + 8) * CH + 8 + 2 * q4);
    }

    // staging roles: 256 threads = 32 pixel-slots x 8 ch-pairs; 2 pixels each
    int pixg = t >> 3;
    int cg   = t & 7;

    float o[2][4];
    float ls0 = 0.f, ls1 = 0.f;
    #pragma unroll
    for (int u = 0; u < 4; u++) { o[0][u] = 0.f; o[1][u] = 0.f; }

    auto ldchunk = [&](int c, float2& fa, float2& fb) {
        int s = sel[c >> 2];
        int jv = (s & 63) >> 3, iv = s & 7;
        const float* base = mv + (size_t)(s >> 6) * 128 * 128 * 128;
        int p0 = (c & 3) * 64 + pixg;
        int p1 = p0 + 32;
        int y0v = jv * 16 + (p0 >> 4), x0v = iv * 16 + (p0 & 15);
        int y1v = jv * 16 + (p1 >> 4), x1v = iv * 16 + (p1 & 15);
        fa = *reinterpret_cast<const float2*>(
            base + ((size_t)y0v * 128 + x0v) * 128 + m * CH + cg * 2);
        fb = *reinterpret_cast<const float2*>(
            base + ((size_t)y1v * 128 + x1v) * 128 + m * CH + cg * 2);
    };
    auto stchunk = [&](int buf, float2 fa, float2 fb) {
        __half2 ha = __floats2half2_rn(fa.x, fa.y);
        __half2 hb = __floats2half2_rn(fb.x, fb.y);
        *reinterpret_cast<__half2*>(kv_s[buf] + pixg * KST + cg * 2) = ha;
        *reinterpret_cast<__half2*>(kv_s[buf] + (pixg + 32) * KST + cg * 2) = hb;
        vt_s[buf][(cg * 2) * VST + pixg]          = __low2half(ha);
        vt_s[buf][(cg * 2 + 1) * VST + pixg]      = __high2half(ha);
        vt_s[buf][(cg * 2) * VST + pixg + 32]     = __low2half(hb);
        vt_s[buf][(cg * 2 + 1) * VST + pixg + 32] = __high2half(hb);
    };

    {
        float2 fa, fb;
        ldchunk(0, fa, fb);
        stchunk(0, fa, fb);
    }
    __syncthreads();

    for (int c = 0; c < 16; c++) {
        int cur = c & 1;
        float2 nfa, nfb;
        if (c + 1 < 16) ldchunk(c + 1, nfa, nfb);   // LDG overlaps compute

        // ---- S = Q K^T (f32 accum) in two 4-nt passes; P = 2^S -> pa ----
        uint32_t pa[4][4];
        #pragma unroll
        for (int g = 0; g < 2; g++) {
            float sc[4][4];
            #pragma unroll
            for (int nt = 0; nt < 4; nt++)
                #pragma unroll
                for (int u = 0; u < 4; u++) sc[nt][u] = 0.f;
            #pragma unroll
            for (int nt = 0; nt < 4; nt++) {
                int ntg = g * 4 + nt;
                const __half* kr = kv_s[cur] + (ntg * 8 + lr) * KST;
                uint32_t b0 = *reinterpret_cast<const uint32_t*>(kr + 2 * q4);
                uint32_t b1 = *reinterpret_cast<const uint32_t*>(kr + 8 + 2 * q4);
                mma_f16(sc[nt], qa, b0, b1, sc[nt]);
            }
            #pragma unroll
            for (int ks = 0; ks < 2; ks++) {
                int kg = g * 2 + ks;
                pa[kg][0] = p_ex2(sc[2 * ks][0],     sc[2 * ks][1]);
                pa[kg][1] = p_ex2(sc[2 * ks][2],     sc[2 * ks][3]);
                pa[kg][2] = p_ex2(sc[2 * ks + 1][0], sc[2 * ks + 1][1]);
                pa[kg][3] = p_ex2(sc[2 * ks + 1][2], sc[2 * ks + 1][3]);
            }
        }

        // ---- O += P V (issue tensor work first) ----
        #pragma unroll
        for (int ks = 0; ks < 4; ks++) {
            #pragma unroll
            for (int nc = 0; nc < 2; nc++) {
                const __half* vr = vt_s[cur] + (nc * 8 + lr) * VST + ks * 16;
                uint32_t b0 = *reinterpret_cast<const uint32_t*>(vr + 2 * q4);
                uint32_t b1 = *reinterpret_cast<const uint32_t*>(vr + 8 + 2 * q4);
                mma_f16(o[nc], pa[ks], b0, b1, o[nc]);
            }
        }

        // ---- row sums on scalar pipes (fills tensor-drain window) ----
        #pragma unroll
        for (int ks = 0; ks < 4; ks++) {
            __half2 w0 = __hadd2(*reinterpret_cast<__half2*>(&pa[ks][0]),
                                 *reinterpret_cast<__half2*>(&pa[ks][2]));
            __half2 w1 = __hadd2(*reinterpret_cast<__half2*>(&pa[ks][1]),
                                 *reinterpret_cast<__half2*>(&pa[ks][3]));
            float2 f0 = __half22float2(w0);
            float2 f1 = __half22float2(w1);
            ls0 += f0.x + f0.y;
            ls1 += f1.x + f1.y;
        }

        if (c + 1 < 16) stchunk((c + 1) & 1, nfa, nfb);
        __syncthreads();
    }

    // ---- epilogue: quad-reduce row sums, normalize, store ----
    ls0 += __shfl_xor_sync(0xffffffffu, ls0, 1);
    ls0 += __shfl_xor_sync(0xffffffffu, ls0, 2);
    ls1 += __shfl_xor_sync(0xffffffffu, ls1, 1);
    ls1 += __shfl_xor_sync(0xffffffffu, ls1, 2);

    #pragma unroll
    for (int h = 0; h < 2; h++) {
        float inv = 1.f / (h ? ls1 : ls0);
        int pix = half * 128 + warp * 16 + h * 8 + lr;
        int hh = pix >> 4, ww = pix & 15;
        float* op = out + ((size_t)(jp * 16 + hh) * 128 + (ip * 16 + ww)) * 128 + m * CH;
        #pragma unroll
        for (int nc = 0; nc < 2; nc++) {
            float2 st;
            st.x = o[nc][2 * h]     * inv;
            st.y = o[nc][2 * h + 1] * inv;
            *reinterpret_cast<float2*>(op + nc * 8 + 2 * q4) = st;
        }
    }
}

extern "C" void kernel_launch(void* const* d_in, const int* in_sizes, int n_in,
                              void* d_out, int out_size) {
    const float* cv = (const float*)d_in[0];   // (1,128,128,128)
    const float* mv = (const float*)d_in[1];   // (1,2,128,128,128)
    float* out = (float*)d_out;                // (1,128,128,128)

    win_mean_kernel<<<192, 1024>>>(cv, mv);
    topk_kernel<<<64, 128>>>();
    dim3 grid(P2, NUM_HEADS, 2);
    attn_kernel<<<grid, 256>>>(cv, mv, out);
}

// round 13
// speedup vs baseline: 3.5401x; 1.0417x over previous
#include <cuda_runtime.h>
#include <cuda_fp16.h>
#include <math_constants.h>
#include <cstdint>

#define NUM_HEADS 8
#define TOPK 4
#define D_MODEL 128
#define CH 16
#define P2 64
#define W2 256
#define NVIEW 2
#define SCALE_LOG2E ((float)(0.08838834764831845 * 1.4426950408889634))
#define KST 24   // kv_s row stride (halves): word=(8nt+lr)*12+q4 -> 32 distinct banks
#define VST 72   // vt_s row stride (halves): word=(4lr+q4) mod 32 -> conflict-free

__device__ float g_qwin[P2 * D_MODEL];
__device__ float g_kwinT[D_MODEL * NVIEW * P2];   // [channel][view*win] transposed
__device__ int   g_ridx[P2 * TOPK];

// pack two f32 -> half2 -> 2^x
__device__ __forceinline__ uint32_t p_ex2(float lo, float hi) {
    uint32_t r;
    asm("{\n\t.reg .b32 t;\n\t"
        "cvt.rn.f16x2.f32 t, %2, %1;\n\t"
        "ex2.approx.f16x2 %0, t;\n\t}"
        : "=r"(r) : "f"(lo), "f"(hi));
    return r;
}

__device__ __forceinline__ void mma_f16(float d[4], const uint32_t a[4],
                                        uint32_t b0, uint32_t b1, const float c[4]) {
    asm volatile(
        "mma.sync.aligned.m16n8k16.row.col.f32.f16.f16.f32 "
        "{%0,%1,%2,%3}, {%4,%5,%6,%7}, {%8,%9}, {%10,%11,%12,%13};"
        : "=f"(d[0]), "=f"(d[1]), "=f"(d[2]), "=f"(d[3])
        : "r"(a[0]), "r"(a[1]), "r"(a[2]), "r"(a[3]), "r"(b0), "r"(b1),
          "f"(c[0]), "f"(c[1]), "f"(c[2]), "f"(c[3]));
}

// ---------------------------------------------------------------------------
// Kernel 1: window means (float4 loads, 1024 threads). k output TRANSPOSED.
// (validated, unchanged)
// ---------------------------------------------------------------------------
__global__ void win_mean_kernel(const float* __restrict__ cv,
                                const float* __restrict__ mv) {
    __shared__ float4 red[1024];
    int b = blockIdx.x;
    int t = threadIdx.x;
    int c4 = t & 31;
    int part = t >> 5;
    const float* src;
    int p;
    bool is_q = (b < P2);
    int widx = 0;
    if (is_q) {
        p = b; src = cv;
    } else {
        int vp = b - P2;
        int v = vp >> 6; p = vp & 63;
        src = mv + (size_t)v * 128 * 128 * 128;
        widx = vp;
    }
    int jp = p >> 3, ip = p & 7;
    int y0 = jp * 16, x0 = ip * 16;
    float4 s = make_float4(0.f, 0.f, 0.f, 0.f);
    #pragma unroll
    for (int u = 0; u < 8; u++) {
        int pix = part * 8 + u;
        int hh = pix >> 4, ww = pix & 15;
        float4 x = *(reinterpret_cast<const float4*>(
            src + ((size_t)(y0 + hh) * 128 + (x0 + ww)) * 128) + c4);
        s.x += x.x; s.y += x.y; s.z += x.z; s.w += x.w;
    }
    red[t] = s;
    __syncthreads();
    if (t < 32) {
        float4 acc = make_float4(0.f, 0.f, 0.f, 0.f);
        #pragma unroll
        for (int k = 0; k < 32; k++) {
            float4 x = red[k * 32 + t];
            acc.x += x.x; acc.y += x.y; acc.z += x.z; acc.w += x.w;
        }
        const float inv = 1.f / 256.f;
        acc.x *= inv; acc.y *= inv; acc.z *= inv; acc.w *= inv;
        if (is_q) {
            reinterpret_cast<float4*>(g_qwin + p * D_MODEL)[t] = acc;
        } else {
            g_kwinT[(4 * t + 0) * 128 + widx] = acc.x;
            g_kwinT[(4 * t + 1) * 128 + widx] = acc.y;
            g_kwinT[(4 * t + 2) * 128 + widx] = acc.z;
            g_kwinT[(4 * t + 3) * 128 + widx] = acc.w;
        }
    }
}

// ---------------------------------------------------------------------------
// Kernel 2: routing + top-4, coalesced kT. (validated, unchanged)
// ---------------------------------------------------------------------------
__global__ void topk_kernel() {
    __shared__ float q_s[D_MODEL];
    __shared__ float logit[128];
    int row = blockIdx.x;
    int t = threadIdx.x;

    q_s[t] = g_qwin[row * D_MODEL + t];
    __syncthreads();

    float s = 0.f;
    #pragma unroll 16
    for (int c = 0; c < D_MODEL; c++)
        s += q_s[c] * g_kwinT[c * 128 + t];
    logit[t] = s;
    __syncthreads();

    if (t < 32) {
        float v[4]; int id[4];
        #pragma unroll
        for (int kloc = 0; kloc < 4; kloc++) {
            int j = t * 4 + kloc;
            v[kloc] = logit[j]; id[kloc] = j;
        }
        #pragma unroll
        for (int r = 0; r < TOPK; r++) {
            float bv = v[0]; int bi = id[0];
            #pragma unroll
            for (int kloc = 1; kloc < 4; kloc++)
                if (v[kloc] > bv || (v[kloc] == bv && id[kloc] < bi)) { bv = v[kloc]; bi = id[kloc]; }
            float wv = bv; int wi = bi;
            #pragma unroll
            for (int off = 16; off; off >>= 1) {
                float ov = __shfl_down_sync(0xffffffffu, wv, off);
                int   oi = __shfl_down_sync(0xffffffffu, wi, off);
                if (ov > wv || (ov == wv && oi < wi)) { wv = ov; wi = oi; }
            }
            wi = __shfl_sync(0xffffffffu, wi, 0);
            if ((wi >> 2) == t) v[wi & 3] = -CUDART_INF_F;
            if (t == 0) g_ridx[row * TOPK + r] = wi;
        }
    }
}

// ---------------------------------------------------------------------------
// Kernel 3: fp16 attention. CHANGE vs 52.0us baseline: z-split merged.
// Grid (64,8): one CTA per (window, head) does ALL 256 q rows; each warp owns
// 32 rows (two m16 tiles). KV staged ONCE per (window, head): staging, L2
// traffic and barriers halve chip-wide. occ 2 (128-reg cap).
// ---------------------------------------------------------------------------
__global__ void __launch_bounds__(256, 2)
attn_kernel(const float* __restrict__ cv,
            const float* __restrict__ mv,
            float* __restrict__ out) {
    int p = blockIdx.x;      // window
    int m = blockIdx.y;      // head
    int t = threadIdx.x;
    int warp = t >> 5, lane = t & 31;
    int lr = lane >> 2, q4 = lane & 3;

    __shared__ __half q_s[W2 * CH];          // 8 KB
    __shared__ __half kv_s[2][64 * KST];     // 2 x 3 KB (k-major, padded)
    __shared__ __half vt_s[2][CH * VST];     // 2 x 2.25 KB (transposed)
    __shared__ int sel_s[TOPK];

    int jp = p >> 3, ip = p & 7;

    // ---- stage Q: all 256 pixels ----
    {
        int hh = t >> 4, ww = t & 15;
        const float4* gp = reinterpret_cast<const float4*>(
            cv + ((size_t)(jp * 16 + hh) * 128 + (ip * 16 + ww)) * 128 + m * CH);
        float4 x0 = gp[0], x1 = gp[1], x2 = gp[2], x3 = gp[3];
        const float s = SCALE_LOG2E;
        __half2* dst = reinterpret_cast<__half2*>(q_s + t * CH);
        dst[0] = __floats2half2_rn(x0.x * s, x0.y * s);
        dst[1] = __floats2half2_rn(x0.z * s, x0.w * s);
        dst[2] = __floats2half2_rn(x1.x * s, x1.y * s);
        dst[3] = __floats2half2_rn(x1.z * s, x1.w * s);
        dst[4] = __floats2half2_rn(x2.x * s, x2.y * s);
        dst[5] = __floats2half2_rn(x2.z * s, x2.w * s);
        dst[6] = __floats2half2_rn(x3.x * s, x3.y * s);
        dst[7] = __floats2half2_rn(x3.z * s, x3.w * s);
    }
    if (t < TOPK) sel_s[t] = g_ridx[p * TOPK + t];
    __syncthreads();

    int sel[TOPK];
    #pragma unroll
    for (int k = 0; k < TOPK; k++) sel[k] = sel_s[k];

    // ---- Q a-frags: two m16 tiles per warp ----
    uint32_t qa[2][4];
    #pragma unroll
    for (int mt = 0; mt < 2; mt++) {
        int r0 = warp * 32 + mt * 16 + lr;
        qa[mt][0] = *reinterpret_cast<const uint32_t*>(q_s + r0 * CH + 2 * q4);
        qa[mt][1] = *reinterpret_cast<const uint32_t*>(q_s + (r0 + 8) * CH + 2 * q4);
        qa[mt][2] = *reinterpret_cast<const uint32_t*>(q_s + r0 * CH + 8 + 2 * q4);
        qa[mt][3] = *reinterpret_cast<const uint32_t*>(q_s + (r0 + 8) * CH + 8 + 2 * q4);
    }

    // staging roles: 256 threads = 32 pixel-slots x 8 ch-pairs; 2 pixels each
    int pixg = t >> 3;
    int cg   = t & 7;

    float o[2][2][4];      // [mtile][nc][4]
    float ls[2][2];        // [mtile][half]
    #pragma unroll
    for (int mt = 0; mt < 2; mt++) {
        ls[mt][0] = 0.f; ls[mt][1] = 0.f;
        #pragma unroll
        for (int u = 0; u < 4; u++) { o[mt][0][u] = 0.f; o[mt][1][u] = 0.f; }
    }

    auto ldchunk = [&](int c, float2& fa, float2& fb) {
        int s = sel[c >> 2];
        int jv = (s & 63) >> 3, iv = s & 7;
        const float* base = mv + (size_t)(s >> 6) * 128 * 128 * 128;
        int p0 = (c & 3) * 64 + pixg;
        int p1 = p0 + 32;
        int y0v = jv * 16 + (p0 >> 4), x0v = iv * 16 + (p0 & 15);
        int y1v = jv * 16 + (p1 >> 4), x1v = iv * 16 + (p1 & 15);
        fa = *reinterpret_cast<const float2*>(
            base + ((size_t)y0v * 128 + x0v) * 128 + m * CH + cg * 2);
        fb = *reinterpret_cast<const float2*>(
            base + ((size_t)y1v * 128 + x1v) * 128 + m * CH + cg * 2);
    };
    auto stchunk = [&](int buf, float2 fa, float2 fb) {
        __half2 ha = __floats2half2_rn(fa.x, fa.y);
        __half2 hb = __floats2half2_rn(fb.x, fb.y);
        *reinterpret_cast<__half2*>(kv_s[buf] + pixg * KST + cg * 2) = ha;
        *reinterpret_cast<__half2*>(kv_s[buf] + (pixg + 32) * KST + cg * 2) = hb;
        vt_s[buf][(cg * 2) * VST + pixg]          = __low2half(ha);
        vt_s[buf][(cg * 2 + 1) * VST + pixg]      = __high2half(ha);
        vt_s[buf][(cg * 2) * VST + pixg + 32]     = __low2half(hb);
        vt_s[buf][(cg * 2 + 1) * VST + pixg + 32] = __high2half(hb);
    };

    {
        float2 fa, fb;
        ldchunk(0, fa, fb);
        stchunk(0, fa, fb);
    }
    __syncthreads();

    for (int c = 0; c < 16; c++) {
        int cur = c & 1;
        float2 nfa, nfb;
        if (c + 1 < 16) ldchunk(c + 1, nfa, nfb);   // LDG overlaps 2x compute

        #pragma unroll
        for (int mt = 0; mt < 2; mt++) {
            // ---- S = Q K^T (f32 accum) in two 4-nt passes; P = 2^S -> pa ----
            uint32_t pa[4][4];
            #pragma unroll
            for (int g = 0; g < 2; g++) {
                float sc[4][4];
                #pragma unroll
                for (int nt = 0; nt < 4; nt++)
                    #pragma unroll
                    for (int u = 0; u < 4; u++) sc[nt][u] = 0.f;
                #pragma unroll
                for (int nt = 0; nt < 4; nt++) {
                    int ntg = g * 4 + nt;
                    const __half* kr = kv_s[cur] + (ntg * 8 + lr) * KST;
                    uint32_t b0 = *reinterpret_cast<const uint32_t*>(kr + 2 * q4);
                    uint32_t b1 = *reinterpret_cast<const uint32_t*>(kr + 8 + 2 * q4);
                    mma_f16(sc[nt], qa[mt], b0, b1, sc[nt]);
                }
                #pragma unroll
                for (int ks = 0; ks < 2; ks++) {
                    int kg = g * 2 + ks;
                    pa[kg][0] = p_ex2(sc[2 * ks][0],     sc[2 * ks][1]);
                    pa[kg][1] = p_ex2(sc[2 * ks][2],     sc[2 * ks][3]);
                    pa[kg][2] = p_ex2(sc[2 * ks + 1][0], sc[2 * ks + 1][1]);
                    pa[kg][3] = p_ex2(sc[2 * ks + 1][2], sc[2 * ks + 1][3]);
                }
            }

            // ---- O += P V ----
            #pragma unroll
            for (int ks = 0; ks < 4; ks++) {
                #pragma unroll
                for (int nc = 0; nc < 2; nc++) {
                    const __half* vr = vt_s[cur] + (nc * 8 + lr) * VST + ks * 16;
                    uint32_t b0 = *reinterpret_cast<const uint32_t*>(vr + 2 * q4);
                    uint32_t b1 = *reinterpret_cast<const uint32_t*>(vr + 8 + 2 * q4);
                    mma_f16(o[mt][nc], pa[ks], b0, b1, o[mt][nc]);
                }
            }

            // ---- row sums on scalar pipes (fills tensor-drain window) ----
            #pragma unroll
            for (int ks = 0; ks < 4; ks++) {
                __half2 w0 = __hadd2(*reinterpret_cast<__half2*>(&pa[ks][0]),
                                     *reinterpret_cast<__half2*>(&pa[ks][2]));
                __half2 w1 = __hadd2(*reinterpret_cast<__half2*>(&pa[ks][1]),
                                     *reinterpret_cast<__half2*>(&pa[ks][3]));
                float2 f0 = __half22float2(w0);
                float2 f1 = __half22float2(w1);
                ls[mt][0] += f0.x + f0.y;
                ls[mt][1] += f1.x + f1.y;
            }
        }

        if (c + 1 < 16) stchunk((c + 1) & 1, nfa, nfb);
        __syncthreads();
    }

    // ---- epilogue: quad-reduce row sums, normalize, store ----
    #pragma unroll
    for (int mt = 0; mt < 2; mt++) {
        #pragma unroll
        for (int h = 0; h < 2; h++) {
            float lt = ls[mt][h];
            lt += __shfl_xor_sync(0xffffffffu, lt, 1);
            lt += __shfl_xor_sync(0xffffffffu, lt, 2);
            float inv = 1.f / lt;
            int pix = warp * 32 + mt * 16 + h * 8 + lr;
            int hh = pix >> 4, ww = pix & 15;
            float* op = out + ((size_t)(jp * 16 + hh) * 128 + (ip * 16 + ww)) * 128 + m * CH;
            #pragma unroll
            for (int nc = 0; nc < 2; nc++) {
                float2 st;
                st.x = o[mt][nc][2 * h]     * inv;
                st.y = o[mt][nc][2 * h + 1] * inv;
                *reinterpret_cast<float2*>(op + nc * 8 + 2 * q4) = st;
            }
        }
    }
}

extern "C" void kernel_launch(void* const* d_in, const int* in_sizes, int n_in,
                              void* d_out, int out_size) {
    const float* cv = (const float*)d_in[0];   // (1,128,128,128)
    const float* mv = (const float*)d_in[1];   // (1,2,128,128,128)
    float* out = (float*)d_out;                // (1,128,128,128)

    win_mean_kernel<<<192, 1024>>>(cv, mv);
    topk_kernel<<<64, 128>>>();
    dim3 grid(P2, NUM_HEADS);
    attn_kernel<<<grid, 256>>>(cv, mv, out);
}

// round 14
// speedup vs baseline: 3.5583x; 1.0052x over previous
#include <cuda_runtime.h>
#include <cuda_fp16.h>
#include <math_constants.h>
#include <cstdint>

#define NUM_HEADS 8
#define TOPK 4
#define D_MODEL 128
#define CH 16
#define P2 64
#define W2 256
#define NVIEW 2
#define SCALE_LOG2E ((float)(0.08838834764831845 * 1.4426950408889634))
#define KST 24   // kv_s row stride (halves): word=(8nt+lr)*12+q4 -> 32 distinct banks
#define VST 72   // vt_s row stride (halves): word=(4lr+q4) mod 32 -> conflict-free

__device__ float g_qwin[P2 * D_MODEL];
__device__ float g_kwinT[D_MODEL * NVIEW * P2];   // [channel][view*win] transposed
__device__ int   g_ridx[P2 * TOPK];

// pack two f32 -> half2 -> 2^x
__device__ __forceinline__ uint32_t p_ex2(float lo, float hi) {
    uint32_t r;
    asm("{\n\t.reg .b32 t;\n\t"
        "cvt.rn.f16x2.f32 t, %2, %1;\n\t"
        "ex2.approx.f16x2 %0, t;\n\t}"
        : "=r"(r) : "f"(lo), "f"(hi));
    return r;
}

__device__ __forceinline__ void mma_f16(float d[4], const uint32_t a[4],
                                        uint32_t b0, uint32_t b1, const float c[4]) {
    asm volatile(
        "mma.sync.aligned.m16n8k16.row.col.f32.f16.f16.f32 "
        "{%0,%1,%2,%3}, {%4,%5,%6,%7}, {%8,%9}, {%10,%11,%12,%13};"
        : "=f"(d[0]), "=f"(d[1]), "=f"(d[2]), "=f"(d[3])
        : "r"(a[0]), "r"(a[1]), "r"(a[2]), "r"(a[3]), "r"(b0), "r"(b1),
          "f"(c[0]), "f"(c[1]), "f"(c[2]), "f"(c[3]));
}

// ---------------------------------------------------------------------------
// Kernel 1: window means (float4 loads, 1024 threads). k output TRANSPOSED.
// (validated, unchanged)
// ---------------------------------------------------------------------------
__global__ void win_mean_kernel(const float* __restrict__ cv,
                                const float* __restrict__ mv) {
    __shared__ float4 red[1024];
    int b = blockIdx.x;
    int t = threadIdx.x;
    int c4 = t & 31;
    int part = t >> 5;
    const float* src;
    int p;
    bool is_q = (b < P2);
    int widx = 0;
    if (is_q) {
        p = b; src = cv;
    } else {
        int vp = b - P2;
        int v = vp >> 6; p = vp & 63;
        src = mv + (size_t)v * 128 * 128 * 128;
        widx = vp;
    }
    int jp = p >> 3, ip = p & 7;
    int y0 = jp * 16, x0 = ip * 16;
    float4 s = make_float4(0.f, 0.f, 0.f, 0.f);
    #pragma unroll
    for (int u = 0; u < 8; u++) {
        int pix = part * 8 + u;
        int hh = pix >> 4, ww = pix & 15;
        float4 x = *(reinterpret_cast<const float4*>(
            src + ((size_t)(y0 + hh) * 128 + (x0 + ww)) * 128) + c4);
        s.x += x.x; s.y += x.y; s.z += x.z; s.w += x.w;
    }
    red[t] = s;
    __syncthreads();
    if (t < 32) {
        float4 acc = make_float4(0.f, 0.f, 0.f, 0.f);
        #pragma unroll
        for (int k = 0; k < 32; k++) {
            float4 x = red[k * 32 + t];
            acc.x += x.x; acc.y += x.y; acc.z += x.z; acc.w += x.w;
        }
        const float inv = 1.f / 256.f;
        acc.x *= inv; acc.y *= inv; acc.z *= inv; acc.w *= inv;
        if (is_q) {
            reinterpret_cast<float4*>(g_qwin + p * D_MODEL)[t] = acc;
        } else {
            g_kwinT[(4 * t + 0) * 128 + widx] = acc.x;
            g_kwinT[(4 * t + 1) * 128 + widx] = acc.y;
            g_kwinT[(4 * t + 2) * 128 + widx] = acc.z;
            g_kwinT[(4 * t + 3) * 128 + widx] = acc.w;
        }
    }
}

// ---------------------------------------------------------------------------
// Kernel 2: routing + top-4, coalesced kT. (validated, unchanged)
// ---------------------------------------------------------------------------
__global__ void topk_kernel() {
    __shared__ float q_s[D_MODEL];
    __shared__ float logit[128];
    int row = blockIdx.x;
    int t = threadIdx.x;

    q_s[t] = g_qwin[row * D_MODEL + t];
    __syncthreads();

    float s = 0.f;
    #pragma unroll 16
    for (int c = 0; c < D_MODEL; c++)
        s += q_s[c] * g_kwinT[c * 128 + t];
    logit[t] = s;
    __syncthreads();

    if (t < 32) {
        float v[4]; int id[4];
        #pragma unroll
        for (int kloc = 0; kloc < 4; kloc++) {
            int j = t * 4 + kloc;
            v[kloc] = logit[j]; id[kloc] = j;
        }
        #pragma unroll
        for (int r = 0; r < TOPK; r++) {
            float bv = v[0]; int bi = id[0];
            #pragma unroll
            for (int kloc = 1; kloc < 4; kloc++)
                if (v[kloc] > bv || (v[kloc] == bv && id[kloc] < bi)) { bv = v[kloc]; bi = id[kloc]; }
            float wv = bv; int wi = bi;
            #pragma unroll
            for (int off = 16; off; off >>= 1) {
                float ov = __shfl_down_sync(0xffffffffu, wv, off);
                int   oi = __shfl_down_sync(0xffffffffu, wi, off);
                if (ov > wv || (ov == wv && oi < wi)) { wv = ov; wi = oi; }
            }
            wi = __shfl_sync(0xffffffffu, wi, 0);
            if ((wi >> 2) == t) v[wi & 3] = -CUDART_INF_F;
            if (t == 0) g_ridx[row * TOPK + r] = wi;
        }
    }
}

// ---------------------------------------------------------------------------
// Kernel 3: fp16 attention. CHANGE vs 49.9us baseline: both q-tiles (mt) are
// processed interleaved over SHARED b-fragments — K/V smem reads halve and
// the MMA stream carries two independent accumulator chains.
// Grid (64,8), 256 threads / 8 warps x 32 q-rows, occ 2.
// ---------------------------------------------------------------------------
__global__ void __launch_bounds__(256, 2)
attn_kernel(const float* __restrict__ cv,
            const float* __restrict__ mv,
            float* __restrict__ out) {
    int p = blockIdx.x;      // window
    int m = blockIdx.y;      // head
    int t = threadIdx.x;
    int warp = t >> 5, lane = t & 31;
    int lr = lane >> 2, q4 = lane & 3;

    __shared__ __half q_s[W2 * CH];          // 8 KB
    __shared__ __half kv_s[2][64 * KST];     // 2 x 3 KB (k-major, padded)
    __shared__ __half vt_s[2][CH * VST];     // 2 x 2.25 KB (transposed)
    __shared__ int sel_s[TOPK];

    int jp = p >> 3, ip = p & 7;

    // ---- stage Q: all 256 pixels ----
    {
        int hh = t >> 4, ww = t & 15;
        const float4* gp = reinterpret_cast<const float4*>(
            cv + ((size_t)(jp * 16 + hh) * 128 + (ip * 16 + ww)) * 128 + m * CH);
        float4 x0 = gp[0], x1 = gp[1], x2 = gp[2], x3 = gp[3];
        const float s = SCALE_LOG2E;
        __half2* dst = reinterpret_cast<__half2*>(q_s + t * CH);
        dst[0] = __floats2half2_rn(x0.x * s, x0.y * s);
        dst[1] = __floats2half2_rn(x0.z * s, x0.w * s);
        dst[2] = __floats2half2_rn(x1.x * s, x1.y * s);
        dst[3] = __floats2half2_rn(x1.z * s, x1.w * s);
        dst[4] = __floats2half2_rn(x2.x * s, x2.y * s);
        dst[5] = __floats2half2_rn(x2.z * s, x2.w * s);
        dst[6] = __floats2half2_rn(x3.x * s, x3.y * s);
        dst[7] = __floats2half2_rn(x3.z * s, x3.w * s);
    }
    if (t < TOPK) sel_s[t] = g_ridx[p * TOPK + t];
    __syncthreads();

    int sel[TOPK];
    #pragma unroll
    for (int k = 0; k < TOPK; k++) sel[k] = sel_s[k];

    // ---- Q a-frags: two m16 tiles per warp ----
    uint32_t qa[2][4];
    #pragma unroll
    for (int mt = 0; mt < 2; mt++) {
        int r0 = warp * 32 + mt * 16 + lr;
        qa[mt][0] = *reinterpret_cast<const uint32_t*>(q_s + r0 * CH + 2 * q4);
        qa[mt][1] = *reinterpret_cast<const uint32_t*>(q_s + (r0 + 8) * CH + 2 * q4);
        qa[mt][2] = *reinterpret_cast<const uint32_t*>(q_s + r0 * CH + 8 + 2 * q4);
        qa[mt][3] = *reinterpret_cast<const uint32_t*>(q_s + (r0 + 8) * CH + 8 + 2 * q4);
    }

    // staging roles: 256 threads = 32 pixel-slots x 8 ch-pairs; 2 pixels each
    int pixg = t >> 3;
    int cg   = t & 7;

    float o[2][2][4];      // [mtile][nc][4]
    float ls[2][2];        // [mtile][half]
    #pragma unroll
    for (int mt = 0; mt < 2; mt++) {
        ls[mt][0] = 0.f; ls[mt][1] = 0.f;
        #pragma unroll
        for (int u = 0; u < 4; u++) { o[mt][0][u] = 0.f; o[mt][1][u] = 0.f; }
    }

    auto ldchunk = [&](int c, float2& fa, float2& fb) {
        int s = sel[c >> 2];
        int jv = (s & 63) >> 3, iv = s & 7;
        const float* base = mv + (size_t)(s >> 6) * 128 * 128 * 128;
        int p0 = (c & 3) * 64 + pixg;
        int p1 = p0 + 32;
        int y0v = jv * 16 + (p0 >> 4), x0v = iv * 16 + (p0 & 15);
        int y1v = jv * 16 + (p1 >> 4), x1v = iv * 16 + (p1 & 15);
        fa = *reinterpret_cast<const float2*>(
            base + ((size_t)y0v * 128 + x0v) * 128 + m * CH + cg * 2);
        fb = *reinterpret_cast<const float2*>(
            base + ((size_t)y1v * 128 + x1v) * 128 + m * CH + cg * 2);
    };
    auto stchunk = [&](int buf, float2 fa, float2 fb) {
        __half2 ha = __floats2half2_rn(fa.x, fa.y);
        __half2 hb = __floats2half2_rn(fb.x, fb.y);
        *reinterpret_cast<__half2*>(kv_s[buf] + pixg * KST + cg * 2) = ha;
        *reinterpret_cast<__half2*>(kv_s[buf] + (pixg + 32) * KST + cg * 2) = hb;
        vt_s[buf][(cg * 2) * VST + pixg]          = __low2half(ha);
        vt_s[buf][(cg * 2 + 1) * VST + pixg]      = __high2half(ha);
        vt_s[buf][(cg * 2) * VST + pixg + 32]     = __low2half(hb);
        vt_s[buf][(cg * 2 + 1) * VST + pixg + 32] = __high2half(hb);
    };

    {
        float2 fa, fb;
        ldchunk(0, fa, fb);
        stchunk(0, fa, fb);
    }
    __syncthreads();

    for (int c = 0; c < 16; c++) {
        int cur = c & 1;
        float2 nfa, nfb;
        if (c + 1 < 16) ldchunk(c + 1, nfa, nfb);   // LDG overlaps compute

        // ---- S = Q K^T for BOTH tiles over shared K b-frags ----
        uint32_t pa[2][4][4];
        #pragma unroll
        for (int g = 0; g < 2; g++) {
            float sc0[4][4], sc1[4][4];
            #pragma unroll
            for (int nt = 0; nt < 4; nt++)
                #pragma unroll
                for (int u = 0; u < 4; u++) { sc0[nt][u] = 0.f; sc1[nt][u] = 0.f; }
            #pragma unroll
            for (int nt = 0; nt < 4; nt++) {
                int ntg = g * 4 + nt;
                const __half* kr = kv_s[cur] + (ntg * 8 + lr) * KST;
                uint32_t b0 = *reinterpret_cast<const uint32_t*>(kr + 2 * q4);
                uint32_t b1 = *reinterpret_cast<const uint32_t*>(kr + 8 + 2 * q4);
                mma_f16(sc0[nt], qa[0], b0, b1, sc0[nt]);
                mma_f16(sc1[nt], qa[1], b0, b1, sc1[nt]);
            }
            #pragma unroll
            for (int ks = 0; ks < 2; ks++) {
                int kg = g * 2 + ks;
                pa[0][kg][0] = p_ex2(sc0[2 * ks][0],     sc0[2 * ks][1]);
                pa[0][kg][1] = p_ex2(sc0[2 * ks][2],     sc0[2 * ks][3]);
                pa[0][kg][2] = p_ex2(sc0[2 * ks + 1][0], sc0[2 * ks + 1][1]);
                pa[0][kg][3] = p_ex2(sc0[2 * ks + 1][2], sc0[2 * ks + 1][3]);
                pa[1][kg][0] = p_ex2(sc1[2 * ks][0],     sc1[2 * ks][1]);
                pa[1][kg][1] = p_ex2(sc1[2 * ks][2],     sc1[2 * ks][3]);
                pa[1][kg][2] = p_ex2(sc1[2 * ks + 1][0], sc1[2 * ks + 1][1]);
                pa[1][kg][3] = p_ex2(sc1[2 * ks + 1][2], sc1[2 * ks + 1][3]);
            }
        }

        // ---- O += P V for BOTH tiles over shared V b-frags ----
        #pragma unroll
        for (int ks = 0; ks < 4; ks++) {
            #pragma unroll
            for (int nc = 0; nc < 2; nc++) {
                const __half* vr = vt_s[cur] + (nc * 8 + lr) * VST + ks * 16;
                uint32_t b0 = *reinterpret_cast<const uint32_t*>(vr + 2 * q4);
                uint32_t b1 = *reinterpret_cast<const uint32_t*>(vr + 8 + 2 * q4);
                mma_f16(o[0][nc], pa[0][ks], b0, b1, o[0][nc]);
                mma_f16(o[1][nc], pa[1][ks], b0, b1, o[1][nc]);
            }
        }

        // ---- row sums on scalar pipes (fills tensor-drain window) ----
        #pragma unroll
        for (int mt = 0; mt < 2; mt++) {
            #pragma unroll
            for (int ks = 0; ks < 4; ks++) {
                __half2 w0 = __hadd2(*reinterpret_cast<__half2*>(&pa[mt][ks][0]),
                                     *reinterpret_cast<__half2*>(&pa[mt][ks][2]));
                __half2 w1 = __hadd2(*reinterpret_cast<__half2*>(&pa[mt][ks][1]),
                                     *reinterpret_cast<__half2*>(&pa[mt][ks][3]));
                float2 f0 = __half22float2(w0);
                float2 f1 = __half22float2(w1);
                ls[mt][0] += f0.x + f0.y;
                ls[mt][1] += f1.x + f1.y;
            }
        }

        if (c + 1 < 16) stchunk((c + 1) & 1, nfa, nfb);
        __syncthreads();
    }

    // ---- epilogue: quad-reduce row sums, normalize, store ----
    #pragma unroll
    for (int mt = 0; mt < 2; mt++) {
        #pragma unroll
        for (int h = 0; h < 2; h++) {
            float lt = ls[mt][h];
            lt += __shfl_xor_sync(0xffffffffu, lt, 1);
            lt += __shfl_xor_sync(0xffffffffu, lt, 2);
            float inv = 1.f / lt;
            int pix = warp * 32 + mt * 16 + h * 8 + lr;
            int hh = pix >> 4, ww = pix & 15;
            float* op = out + ((size_t)(jp * 16 + hh) * 128 + (ip * 16 + ww)) * 128 + m * CH;
            #pragma unroll
            for (int nc = 0; nc < 2; nc++) {
                float2 st;
                st.x = o[mt][nc][2 * h]     * inv;
                st.y = o[mt][nc][2 * h + 1] * inv;
                *reinterpret_cast<float2*>(op + nc * 8 + 2 * q4) = st;
            }
        }
    }
}

extern "C" void kernel_launch(void* const* d_in, const int* in_sizes, int n_in,
                              void* d_out, int out_size) {
    const float* cv = (const float*)d_in[0];   // (1,128,128,128)
    const float* mv = (const float*)d_in[1];   // (1,2,128,128,128)
    float* out = (float*)d_out;                // (1,128,128,128)

    win_mean_kernel<<<192, 1024>>>(cv, mv);
    topk_kernel<<<64, 128>>>();
    dim3 grid(P2, NUM_HEADS);
    attn_kernel<<<grid, 256>>>(cv, mv, out);
}

// round 15
// speedup vs baseline: 3.7090x; 1.0423x over previous
#include <cuda_runtime.h>
#include <cuda_fp16.h>
#include <math_constants.h>
#include <cstdint>

#define NUM_HEADS 8
#define TOPK 4
#define D_MODEL 128
#define CH 16
#define P2 64
#define W2 256
#define NVIEW 2
#define SCALE_LOG2E ((float)(0.08838834764831845 * 1.4426950408889634))
#define KST 24   // kv_s row stride (halves): word=row*12+q4 -> 32 distinct banks
#define VST 72   // vt_s row stride (halves): word=(4lr+q4) mod 32 -> conflict-free

__device__ float g_qwin[P2 * D_MODEL];
__device__ float g_kwinT[D_MODEL * NVIEW * P2];   // [channel][view*win] transposed
__device__ int   g_ridx[P2 * TOPK];

// pack two f32 -> half2 -> 2^x
__device__ __forceinline__ uint32_t p_ex2(float lo, float hi) {
    uint32_t r;
    asm("{\n\t.reg .b32 t;\n\t"
        "cvt.rn.f16x2.f32 t, %2, %1;\n\t"
        "ex2.approx.f16x2 %0, t;\n\t}"
        : "=r"(r) : "f"(lo), "f"(hi));
    return r;
}

__device__ __forceinline__ void mma_f16(float d[4], const uint32_t a[4],
                                        uint32_t b0, uint32_t b1, const float c[4]) {
    asm volatile(
        "mma.sync.aligned.m16n8k16.row.col.f32.f16.f16.f32 "
        "{%0,%1,%2,%3}, {%4,%5,%6,%7}, {%8,%9}, {%10,%11,%12,%13};"
        : "=f"(d[0]), "=f"(d[1]), "=f"(d[2]), "=f"(d[3])
        : "r"(a[0]), "r"(a[1]), "r"(a[2]), "r"(a[3]), "r"(b0), "r"(b1),
          "f"(c[0]), "f"(c[1]), "f"(c[2]), "f"(c[3]));
}

// ---------------------------------------------------------------------------
// Kernel 1: window means (float4 loads, 1024 threads). k output TRANSPOSED.
// (validated, unchanged)
// ---------------------------------------------------------------------------
__global__ void win_mean_kernel(const float* __restrict__ cv,
                                const float* __restrict__ mv) {
    __shared__ float4 red[1024];
    int b = blockIdx.x;
    int t = threadIdx.x;
    int c4 = t & 31;
    int part = t >> 5;
    const float* src;
    int p;
    bool is_q = (b < P2);
    int widx = 0;
    if (is_q) {
        p = b; src = cv;
    } else {
        int vp = b - P2;
        int v = vp >> 6; p = vp & 63;
        src = mv + (size_t)v * 128 * 128 * 128;
        widx = vp;
    }
    int jp = p >> 3, ip = p & 7;
    int y0 = jp * 16, x0 = ip * 16;
    float4 s = make_float4(0.f, 0.f, 0.f, 0.f);
    #pragma unroll
    for (int u = 0; u < 8; u++) {
        int pix = part * 8 + u;
        int hh = pix >> 4, ww = pix & 15;
        float4 x = *(reinterpret_cast<const float4*>(
            src + ((size_t)(y0 + hh) * 128 + (x0 + ww)) * 128) + c4);
        s.x += x.x; s.y += x.y; s.z += x.z; s.w += x.w;
    }
    red[t] = s;
    __syncthreads();
    if (t < 32) {
        float4 acc = make_float4(0.f, 0.f, 0.f, 0.f);
        #pragma unroll
        for (int k = 0; k < 32; k++) {
            float4 x = red[k * 32 + t];
            acc.x += x.x; acc.y += x.y; acc.z += x.z; acc.w += x.w;
        }
        const float inv = 1.f / 256.f;
        acc.x *= inv; acc.y *= inv; acc.z *= inv; acc.w *= inv;
        if (is_q) {
            reinterpret_cast<float4*>(g_qwin + p * D_MODEL)[t] = acc;
        } else {
            g_kwinT[(4 * t + 0) * 128 + widx] = acc.x;
            g_kwinT[(4 * t + 1) * 128 + widx] = acc.y;
            g_kwinT[(4 * t + 2) * 128 + widx] = acc.z;
            g_kwinT[(4 * t + 3) * 128 + widx] = acc.w;
        }
    }
}

// ---------------------------------------------------------------------------
// Kernel 2: routing + top-4, coalesced kT. (validated, unchanged)
// ---------------------------------------------------------------------------
__global__ void topk_kernel() {
    __shared__ float q_s[D_MODEL];
    __shared__ float logit[128];
    int row = blockIdx.x;
    int t = threadIdx.x;

    q_s[t] = g_qwin[row * D_MODEL + t];
    __syncthreads();

    float s = 0.f;
    #pragma unroll 16
    for (int c = 0; c < D_MODEL; c++)
        s += q_s[c] * g_kwinT[c * 128 + t];
    logit[t] = s;
    __syncthreads();

    if (t < 32) {
        float v[4]; int id[4];
        #pragma unroll
        for (int kloc = 0; kloc < 4; kloc++) {
            int j = t * 4 + kloc;
            v[kloc] = logit[j]; id[kloc] = j;
        }
        #pragma unroll
        for (int r = 0; r < TOPK; r++) {
            float bv = v[0]; int bi = id[0];
            #pragma unroll
            for (int kloc = 1; kloc < 4; kloc++)
                if (v[kloc] > bv || (v[kloc] == bv && id[kloc] < bi)) { bv = v[kloc]; bi = id[kloc]; }
            float wv = bv; int wi = bi;
            #pragma unroll
            for (int off = 16; off; off >>= 1) {
                float ov = __shfl_down_sync(0xffffffffu, wv, off);
                int   oi = __shfl_down_sync(0xffffffffu, wi, off);
                if (ov > wv || (ov == wv && oi < wi)) { wv = ov; wi = oi; }
            }
            wi = __shfl_sync(0xffffffffu, wi, 0);
            if ((wi >> 2) == t) v[wi & 3] = -CUDART_INF_F;
            if (t == 0) g_ridx[row * TOPK + r] = wi;
        }
    }
}

// ---------------------------------------------------------------------------
// Kernel 3: fp16 attention. CHANGE vs 49.6us baseline: 8 outer chunks of 128
// kv rows (one barrier each, was 16), two 64-row interleaved-mt compute
// passes per barrier. Grid (64,8), 256 threads / 8 warps x 32 q-rows, occ 2.
// ---------------------------------------------------------------------------
__global__ void __launch_bounds__(256, 2)
attn_kernel(const float* __restrict__ cv,
            const float* __restrict__ mv,
            float* __restrict__ out) {
    int p = blockIdx.x;      // window
    int m = blockIdx.y;      // head
    int t = threadIdx.x;
    int warp = t >> 5, lane = t & 31;
    int lr = lane >> 2, q4 = lane & 3;

    __shared__ __half q_s[W2 * CH];           // 8 KB
    __shared__ __half kv_s[2][128 * KST];     // 2 x 6 KB (k-major, padded)
    __shared__ __half vt_s[2][2][CH * VST];   // 2 buf x 2 sub x 2.25 KB
    __shared__ int sel_s[TOPK];

    int jp = p >> 3, ip = p & 7;

    // ---- stage Q: all 256 pixels ----
    {
        int hh = t >> 4, ww = t & 15;
        const float4* gp = reinterpret_cast<const float4*>(
            cv + ((size_t)(jp * 16 + hh) * 128 + (ip * 16 + ww)) * 128 + m * CH);
        float4 x0 = gp[0], x1 = gp[1], x2 = gp[2], x3 = gp[3];
        const float s = SCALE_LOG2E;
        __half2* dst = reinterpret_cast<__half2*>(q_s + t * CH);
        dst[0] = __floats2half2_rn(x0.x * s, x0.y * s);
        dst[1] = __floats2half2_rn(x0.z * s, x0.w * s);
        dst[2] = __floats2half2_rn(x1.x * s, x1.y * s);
        dst[3] = __floats2half2_rn(x1.z * s, x1.w * s);
        dst[4] = __floats2half2_rn(x2.x * s, x2.y * s);
        dst[5] = __floats2half2_rn(x2.z * s, x2.w * s);
        dst[6] = __floats2half2_rn(x3.x * s, x3.y * s);
        dst[7] = __floats2half2_rn(x3.z * s, x3.w * s);
    }
    if (t < TOPK) sel_s[t] = g_ridx[p * TOPK + t];
    __syncthreads();

    int sel[TOPK];
    #pragma unroll
    for (int k = 0; k < TOPK; k++) sel[k] = sel_s[k];

    // ---- Q a-frags: two m16 tiles per warp ----
    uint32_t qa[2][4];
    #pragma unroll
    for (int mt = 0; mt < 2; mt++) {
        int r0 = warp * 32 + mt * 16 + lr;
        qa[mt][0] = *reinterpret_cast<const uint32_t*>(q_s + r0 * CH + 2 * q4);
        qa[mt][1] = *reinterpret_cast<const uint32_t*>(q_s + (r0 + 8) * CH + 2 * q4);
        qa[mt][2] = *reinterpret_cast<const uint32_t*>(q_s + r0 * CH + 8 + 2 * q4);
        qa[mt][3] = *reinterpret_cast<const uint32_t*>(q_s + (r0 + 8) * CH + 8 + 2 * q4);
    }

    // staging roles: 256 threads = 32 pixel-slots x 8 ch-pairs; 4 pixels each
    int pixg = t >> 3;
    int cg   = t & 7;

    float o[2][2][4];      // [mtile][nc][4]
    float ls[2][2];        // [mtile][half]
    #pragma unroll
    for (int mt = 0; mt < 2; mt++) {
        ls[mt][0] = 0.f; ls[mt][1] = 0.f;
        #pragma unroll
        for (int u = 0; u < 4; u++) { o[mt][0][u] = 0.f; o[mt][1][u] = 0.f; }
    }

    // outer chunk c: kv rows [c*128, c*128+128) = window sel[c>>1], off (c&1)*128
    auto ldchunk = [&](int c, float2 f[4]) {
        int s = sel[c >> 1];
        int jv = (s & 63) >> 3, iv = s & 7;
        const float* base = mv + (size_t)(s >> 6) * 128 * 128 * 128;
        int goff = (c & 1) * 128;
        #pragma unroll
        for (int k = 0; k < 4; k++) {
            int pixl = goff + pixg + 32 * k;
            int yy = jv * 16 + (pixl >> 4), xx = iv * 16 + (pixl & 15);
            f[k] = *reinterpret_cast<const float2*>(
                base + ((size_t)yy * 128 + xx) * 128 + m * CH + cg * 2);
        }
    };
    auto stchunk = [&](int buf, const float2 f[4]) {
        #pragma unroll
        for (int k = 0; k < 4; k++) {
            int pix = pixg + 32 * k;
            __half2 h = __floats2half2_rn(f[k].x, f[k].y);
            *reinterpret_cast<__half2*>(kv_s[buf] + pix * KST + cg * 2) = h;
            __half* vt = vt_s[buf][k >> 1];
            int col = pix & 63;
            vt[(cg * 2) * VST + col]     = __low2half(h);
            vt[(cg * 2 + 1) * VST + col] = __high2half(h);
        }
    };

    {
        float2 f[4];
        ldchunk(0, f);
        stchunk(0, f);
    }
    __syncthreads();

    for (int c = 0; c < 8; c++) {
        int cur = c & 1;
        float2 nf[4];
        if (c + 1 < 8) ldchunk(c + 1, nf);   // LDG hides under TWO passes

        #pragma unroll
        for (int j = 0; j < 2; j++) {
            // ---- S = Q K^T for BOTH tiles over shared K b-frags ----
            uint32_t pa[2][4][4];
            #pragma unroll
            for (int g = 0; g < 2; g++) {
                float sc0[4][4], sc1[4][4];
                #pragma unroll
                for (int nt = 0; nt < 4; nt++)
                    #pragma unroll
                    for (int u = 0; u < 4; u++) { sc0[nt][u] = 0.f; sc1[nt][u] = 0.f; }
                #pragma unroll
                for (int nt = 0; nt < 4; nt++) {
                    int row = j * 64 + (g * 4 + nt) * 8 + lr;
                    const __half* kr = kv_s[cur] + row * KST;
                    uint32_t b0 = *reinterpret_cast<const uint32_t*>(kr + 2 * q4);
                    uint32_t b1 = *reinterpret_cast<const uint32_t*>(kr + 8 + 2 * q4);
                    mma_f16(sc0[nt], qa[0], b0, b1, sc0[nt]);
                    mma_f16(sc1[nt], qa[1], b0, b1, sc1[nt]);
                }
                #pragma unroll
                for (int ks = 0; ks < 2; ks++) {
                    int kg = g * 2 + ks;
                    pa[0][kg][0] = p_ex2(sc0[2 * ks][0],     sc0[2 * ks][1]);
                    pa[0][kg][1] = p_ex2(sc0[2 * ks][2],     sc0[2 * ks][3]);
                    pa[0][kg][2] = p_ex2(sc0[2 * ks + 1][0], sc0[2 * ks + 1][1]);
                    pa[0][kg][3] = p_ex2(sc0[2 * ks + 1][2], sc0[2 * ks + 1][3]);
                    pa[1][kg][0] = p_ex2(sc1[2 * ks][0],     sc1[2 * ks][1]);
                    pa[1][kg][1] = p_ex2(sc1[2 * ks][2],     sc1[2 * ks][3]);
                    pa[1][kg][2] = p_ex2(sc1[2 * ks + 1][0], sc1[2 * ks + 1][1]);
                    pa[1][kg][3] = p_ex2(sc1[2 * ks + 1][2], sc1[2 * ks + 1][3]);
                }
            }

            // ---- O += P V for BOTH tiles over shared V b-frags ----
            #pragma unroll
            for (int ks = 0; ks < 4; ks++) {
                #pragma unroll
                for (int nc = 0; nc < 2; nc++) {
                    const __half* vr = vt_s[cur][j] + (nc * 8 + lr) * VST + ks * 16;
                    uint32_t b0 = *reinterpret_cast<const uint32_t*>(vr + 2 * q4);
                    uint32_t b1 = *reinterpret_cast<const uint32_t*>(vr + 8 + 2 * q4);
                    mma_f16(o[0][nc], pa[0][ks], b0, b1, o[0][nc]);
                    mma_f16(o[1][nc], pa[1][ks], b0, b1, o[1][nc]);
                }
            }

            // ---- row sums on scalar pipes (fills tensor-drain window) ----
            #pragma unroll
            for (int mt = 0; mt < 2; mt++) {
                #pragma unroll
                for (int ks = 0; ks < 4; ks++) {
                    __half2 w0 = __hadd2(*reinterpret_cast<__half2*>(&pa[mt][ks][0]),
                                         *reinterpret_cast<__half2*>(&pa[mt][ks][2]));
                    __half2 w1 = __hadd2(*reinterpret_cast<__half2*>(&pa[mt][ks][1]),
                                         *reinterpret_cast<__half2*>(&pa[mt][ks][3]));
                    float2 f0 = __half22float2(w0);
                    float2 f1 = __half22float2(w1);
                    ls[mt][0] += f0.x + f0.y;
                    ls[mt][1] += f1.x + f1.y;
                }
            }
        }

        if (c + 1 < 8) stchunk(cur ^ 1, nf);
        __syncthreads();
    }

    // ---- epilogue: quad-reduce row sums, normalize, store ----
    #pragma unroll
    for (int mt = 0; mt < 2; mt++) {
        #pragma unroll
        for (int h = 0; h < 2; h++) {
            float lt = ls[mt][h];
            lt += __shfl_xor_sync(0xffffffffu, lt, 1);
            lt += __shfl_xor_sync(0xffffffffu, lt, 2);
            float inv = 1.f / lt;
            int pix = warp * 32 + mt * 16 + h * 8 + lr;
            int hh = pix >> 4, ww = pix & 15;
            float* op = out + ((size_t)(jp * 16 + hh) * 128 + (ip * 16 + ww)) * 128 + m * CH;
            #pragma unroll
            for (int nc = 0; nc < 2; nc++) {
                float2 st;
                st.x = o[mt][nc][2 * h]     * inv;
                st.y = o[mt][nc][2 * h + 1] * inv;
                *reinterpret_cast<float2*>(op + nc * 8 + 2 * q4) = st;
            }
        }
    }
}

extern "C" void kernel_launch(void* const* d_in, const int* in_sizes, int n_in,
                              void* d_out, int out_size) {
    const float* cv = (const float*)d_in[0];   // (1,128,128,128)
    const float* mv = (const float*)d_in[1];   // (1,2,128,128,128)
    float* out = (float*)d_out;                // (1,128,128,128)

    win_mean_kernel<<<192, 1024>>>(cv, mv);
    topk_kernel<<<64, 128>>>();
    dim3 grid(P2, NUM_HEADS);
    attn_kernel<<<grid, 256>>>(cv, mv, out);
}